// round 11
// baseline (speedup 1.0000x reference)
#include <cuda_runtime.h>
#include <cuda_fp16.h>
#include <math.h>
#include <stdint.h>

#define BATCH 2
#define TT    2048
#define BT    4096
#define CC    512
#define HH    8
#define HDIM  64
#define LLAY  4
#define VV    50257
#define VPAD  50304               // multiple of 128
#define FFD   2048
#define LNEPS 1e-5f
#define BHZ   16
#define GXV   (VPAD/128)          // 393 LM-head col tiles

// ---------------- scratch -----------------------------------------------------
__device__ float  g_h    [BT*CC];
__device__ __half g_ainh [BT*CC];
__device__ float  g_qkv  [BT*3*CC];
__device__ __half g_attnh[BT*CC];
__device__ __half g_ffh  [(size_t)BT*FFD];
__device__ __half g_wqkvT[(size_t)LLAY*3*CC*CC];
__device__ __half g_wpT  [(size_t)LLAY*CC*CC];
__device__ __half g_w1T  [(size_t)LLAY*FFD*CC];
__device__ __half g_w2T  [(size_t)LLAY*CC*FFD];
__device__ __half g_lmwT [(size_t)VPAD*CC];
__device__ float  g_lsem [(size_t)BT*400];         // per-(row, coltile) max
__device__ float  g_lses [(size_t)BT*400];         // per-(row, coltile) sum
__device__ float  g_loss;

// ---------------- helpers ------------------------------------------------------
__device__ __forceinline__ float warpSum(float v) {
    #pragma unroll
    for (int o = 16; o; o >>= 1) v += __shfl_xor_sync(0xffffffffu, v, o);
    return v;
}
__device__ __forceinline__ float tf32r(float x) {
    uint32_t u;
    asm("cvt.rna.tf32.f32 %0, %1;" : "=r"(u) : "f"(x));
    return __uint_as_float(u);
}
__device__ __forceinline__ void mma8(float* c, const uint32_t* a, const uint32_t* b) {
    asm volatile(
        "mma.sync.aligned.m16n8k8.row.col.f32.tf32.tf32.f32 "
        "{%0,%1,%2,%3}, {%4,%5,%6,%7}, {%8,%9}, {%0,%1,%2,%3};"
        : "+f"(c[0]), "+f"(c[1]), "+f"(c[2]), "+f"(c[3])
        : "r"(a[0]), "r"(a[1]), "r"(a[2]), "r"(a[3]), "r"(b[0]), "r"(b[1]));
}
__device__ __forceinline__ void mma16(float* c, const uint32_t* a, const uint32_t* b) {
    asm volatile(
        "mma.sync.aligned.m16n8k16.row.col.f32.f16.f16.f32 "
        "{%0,%1,%2,%3}, {%4,%5,%6,%7}, {%8,%9}, {%0,%1,%2,%3};"
        : "+f"(c[0]), "+f"(c[1]), "+f"(c[2]), "+f"(c[3])
        : "r"(a[0]), "r"(a[1]), "r"(a[2]), "r"(a[3]), "r"(b[0]), "r"(b[1]));
}
__device__ __forceinline__ uint32_t sptr(const void* p) {
    return (uint32_t)__cvta_generic_to_shared(p);
}
#define CP_ASYNC16(d, s) \
    asm volatile("cp.async.ca.shared.global [%0], [%1], 16;\n" :: "r"(d), "l"(s))
#define CP_COMMIT() asm volatile("cp.async.commit_group;\n" ::: "memory")
#define CP_WAIT1()  asm volatile("cp.async.wait_group 1;\n"  ::: "memory")

// ---------------- fused weight prep (single launch) ---------------------------
// 32x32 tiled transposes, region-decoded from flat blockIdx.x
#define T_QKV (48*16*LLAY)        // 3072
#define T_WP  (16*16*LLAY)        // 1024
#define T_W1  (64*16*LLAY)        // 4096
#define T_W2  (16*64*LLAY)        // 4096
#define T_LMW ((VPAD/32)*16)      // 25152
#define T_ALL (T_QKV+T_WP+T_W1+T_W2+T_LMW)

__device__ __forceinline__ void trans_tile(__half* dst, const float* src,
                                           int R, int Creal, int xt, int yt,
                                           float (*t)[33], int tx, int ty) {
    int c0 = xt * 32, r0 = yt * 32;
    #pragma unroll
    for (int i = 0; i < 32; i += 8) {
        int c = c0 + tx;
        t[tx][ty + i] = (c < Creal) ? src[(size_t)(r0 + ty + i) * Creal + c] : 0.f;
    }
    __syncthreads();
    #pragma unroll
    for (int i = 0; i < 32; i += 8)
        dst[(size_t)(c0 + ty + i) * R + r0 + tx] = __float2half_rn(t[ty + i][tx]);
}

__global__ void prep_kernel(const float* __restrict__ wq, const float* __restrict__ wk,
                            const float* __restrict__ wv, const float* __restrict__ wproj,
                            const float* __restrict__ wff1, const float* __restrict__ wff2,
                            const float* __restrict__ lmw) {
    __shared__ float t[32][33];
    int tx = threadIdx.x, ty = threadIdx.y;
    int bid = blockIdx.x;
    if (bid < T_QKV) {
        int l = bid / (48 * 16), rem = bid % (48 * 16);
        int xt = rem % 48, yt = rem / 48;
        int j0 = xt * 32, c0 = yt * 32;
        int which = j0 >> 9, h = (j0 & 511) >> 6, d0 = j0 & 63;
        const float* w = (which == 0) ? wq : (which == 1) ? wk : wv;
        const float* s = w + (((size_t)l * HH + h) * CC) * HDIM;
        #pragma unroll
        for (int i = 0; i < 32; i += 8)
            t[tx][ty + i] = s[(size_t)(c0 + ty + i) * HDIM + d0 + tx];
        __syncthreads();
        __half* d = g_wqkvT + ((size_t)l * (3 * CC) + j0) * CC + c0;
        #pragma unroll
        for (int i = 0; i < 32; i += 8)
            d[(size_t)(ty + i) * CC + tx] = __float2half_rn(t[ty + i][tx]);
        return;
    }
    bid -= T_QKV;
    if (bid < T_WP) {
        int l = bid / 256, rem = bid % 256;
        trans_tile(g_wpT + (size_t)l * CC * CC, wproj + (size_t)l * CC * CC,
                   CC, CC, rem % 16, rem / 16, t, tx, ty);
        return;
    }
    bid -= T_WP;
    if (bid < T_W1) {
        int l = bid / 1024, rem = bid % 1024;
        trans_tile(g_w1T + (size_t)l * FFD * CC, wff1 + (size_t)l * CC * FFD,
                   CC, FFD, rem % 64, rem / 64, t, tx, ty);
        return;
    }
    bid -= T_W1;
    if (bid < T_W2) {
        int l = bid / 1024, rem = bid % 1024;
        trans_tile(g_w2T + (size_t)l * CC * FFD, wff2 + (size_t)l * FFD * CC,
                   FFD, CC, rem % 16, rem / 16, t, tx, ty);
        return;
    }
    bid -= T_W2;
    trans_tile(g_lmwT, lmw, CC, VV, bid % (VPAD / 32), bid / (VPAD / 32), t, tx, ty);
}

// ---------------- embedding / layernorm ---------------------------------------
__global__ void embed_kernel(const int* __restrict__ x, const float* __restrict__ tok,
                             const float* __restrict__ pos) {
    int i = blockIdx.x * blockDim.x + threadIdx.x;
    if (i >= BT * CC) return;
    int c = i % CC, bt = i / CC, t = bt % TT;
    g_h[i] = tok[(size_t)x[bt] * CC + c] + pos[(size_t)t * CC + c];
}

__global__ void ln_kernel(const float* __restrict__ in, const float* __restrict__ sc,
                          const float* __restrict__ bi, __half* __restrict__ out) {
    int row = blockIdx.x, tid = threadIdx.x;
    const float* r = in + (size_t)row * CC;
    float a = r[tid], b = r[tid + 256];
    float s = a + b, q = a * a + b * b;
    s = warpSum(s); q = warpSum(q);
    __shared__ float rs[8], rq[8];
    if ((tid & 31) == 0) { rs[tid >> 5] = s; rq[tid >> 5] = q; }
    __syncthreads();
    __shared__ float s_mean, s_rstd;
    if (tid == 0) {
        float S = 0.f, Q = 0.f;
        #pragma unroll
        for (int i = 0; i < 8; i++) { S += rs[i]; Q += rq[i]; }
        float m = S * (1.0f / CC);
        s_mean = m; s_rstd = rsqrtf(Q * (1.0f / CC) - m * m + LNEPS);
    }
    __syncthreads();
    float m = s_mean, rstd = s_rstd;
    __half* o = out + (size_t)row * CC;
    o[tid]       = __float2half_rn((a - m) * rstd * sc[tid]       + bi[tid]);
    o[tid + 256] = __float2half_rn((b - m) * rstd * sc[tid + 256] + bi[tid + 256]);
}

// ---------------- fp16 GEMM: C[M,N] = A[M,K] @ Bt[N,K]^T ----------------------
// 128x128 tile, BK=32 halves, 256 thr (8 warps 2x4, 64x32 each), 3-stage.
// Optional fused per-row partial logsumexp (LM head) via lsem/lses scratch.
#define ALD 40
#define STGB 20480
#define HSMEM (3*STGB)

__global__ __launch_bounds__(256, 3)
void gemm_fp16_kernel(const __half* __restrict__ A, const __half* __restrict__ Bt,
                      float* __restrict__ Cout, __half* __restrict__ CoutH,
                      int Nreal, int K,
                      const float* __restrict__ bias, const float* __restrict__ res,
                      int relu, int rnd,
                      float* __restrict__ lsem, float* __restrict__ lses, int gx) {
    extern __shared__ __align__(16) char hsm[];
    int tid = threadIdx.x;
    int row0 = blockIdx.y << 7, col0 = blockIdx.x << 7;
    int lane = tid & 31, gid = lane >> 2, tig = lane & 3;
    int wid = tid >> 5;
    int wr = (wid >> 2) * 64;
    int wc = (wid & 3) * 32;

    float acc[4][4][4];
    #pragma unroll
    for (int i = 0; i < 4; i++)
        #pragma unroll
        for (int j = 0; j < 4; j++)
            #pragma unroll
            for (int q = 0; q < 4; q++) acc[i][j][q] = 0.f;

    const __half* Ab = A + (size_t)row0 * K;
    const __half* Bb = Bt + (size_t)col0 * K;
    int r0 = tid >> 2, c0 = tid & 3;
    int r1 = (tid + 256) >> 2, c1 = (tid + 256) & 3;

    #define LOAD_STAGE(st, k0)                                                 \
        do {                                                                   \
            uint32_t as = sptr(hsm) + (st) * STGB;                             \
            uint32_t bs = as + 10240;                                          \
            CP_ASYNC16(as + r0 * 80 + c0 * 16, Ab + (size_t)r0 * K + (k0) + c0 * 8); \
            CP_ASYNC16(as + r1 * 80 + c1 * 16, Ab + (size_t)r1 * K + (k0) + c1 * 8); \
            CP_ASYNC16(bs + r0 * 80 + c0 * 16, Bb + (size_t)r0 * K + (k0) + c0 * 8); \
            CP_ASYNC16(bs + r1 * 80 + c1 * 16, Bb + (size_t)r1 * K + (k0) + c1 * 8); \
        } while (0)

    int ntiles = K >> 5;
    LOAD_STAGE(0, 0);  CP_COMMIT();
    if (ntiles > 1) LOAD_STAGE(1, 32);
    CP_COMMIT();

    int st = 0;
    for (int it = 0; it < ntiles; it++) {
        CP_WAIT1();
        __syncthreads();
        int nx = it + 2;
        int stn = st + 2; if (stn >= 3) stn -= 3;
        if (nx < ntiles) LOAD_STAGE(stn, nx << 5);
        CP_COMMIT();

        const __half* as = (const __half*)(hsm + st * STGB);
        const __half* bs = as + 5120;
        #pragma unroll
        for (int ks = 0; ks < 2; ks++) {
            int kb = ks << 4;
            uint32_t af[4][4], bf[4][2];
            #pragma unroll
            for (int i = 0; i < 4; i++) {
                int m = wr + i * 16 + gid;
                af[i][0] = *(const uint32_t*)&as[(m    ) * ALD + kb + 2 * tig    ];
                af[i][1] = *(const uint32_t*)&as[(m + 8) * ALD + kb + 2 * tig    ];
                af[i][2] = *(const uint32_t*)&as[(m    ) * ALD + kb + 2 * tig + 8];
                af[i][3] = *(const uint32_t*)&as[(m + 8) * ALD + kb + 2 * tig + 8];
            }
            #pragma unroll
            for (int j = 0; j < 4; j++) {
                int n = wc + j * 8 + gid;
                bf[j][0] = *(const uint32_t*)&bs[n * ALD + kb + 2 * tig    ];
                bf[j][1] = *(const uint32_t*)&bs[n * ALD + kb + 2 * tig + 8];
            }
            #pragma unroll
            for (int i = 0; i < 4; i++)
                #pragma unroll
                for (int j = 0; j < 4; j++)
                    mma16(acc[i][j], af[i], bf[j]);
        }
        if (++st == 3) st = 0;
    }
    #undef LOAD_STAGE

    // apply bias/res/relu in-place so acc holds final values
    #pragma unroll
    for (int i = 0; i < 4; i++)
        #pragma unroll
        for (int j = 0; j < 4; j++) {
            int cc0 = col0 + wc + j * 8 + tig * 2;
            #pragma unroll
            for (int h2 = 0; h2 < 2; h2++) {
                int r = row0 + wr + i * 16 + gid + h2 * 8;
                float v0 = acc[i][j][h2 * 2 + 0];
                float v1 = acc[i][j][h2 * 2 + 1];
                if (cc0 < Nreal) {
                    if (bias) v0 += bias[cc0];
                    if (res)  v0 += res[(size_t)r * Nreal + cc0];
                    if (relu) v0 = fmaxf(v0, 0.f);
                    acc[i][j][h2 * 2 + 0] = v0;
                    if (CoutH) CoutH[(size_t)r * Nreal + cc0] = __float2half_rn(v0);
                    else       Cout [(size_t)r * Nreal + cc0] = rnd ? tf32r(v0) : v0;
                }
                if (cc0 + 1 < Nreal) {
                    if (bias) v1 += bias[cc0 + 1];
                    if (res)  v1 += res[(size_t)r * Nreal + cc0 + 1];
                    if (relu) v1 = fmaxf(v1, 0.f);
                    acc[i][j][h2 * 2 + 1] = v1;
                    if (CoutH) CoutH[(size_t)r * Nreal + cc0 + 1] = __float2half_rn(v1);
                    else       Cout [(size_t)r * Nreal + cc0 + 1] = rnd ? tf32r(v1) : v1;
                }
            }
        }

    // fused partial logsumexp over this CTA's 128 columns (LM head only)
    if (lsem) {
        float2* sls = (float2*)hsm;        // [128 rows][4 wc-groups]
        __syncthreads();                   // mainloop smem fully consumed
        #pragma unroll
        for (int i = 0; i < 4; i++)
            #pragma unroll
            for (int h2 = 0; h2 < 2; h2++) {
                float m = -1e30f;
                #pragma unroll
                for (int j = 0; j < 4; j++) {
                    int c = col0 + wc + j * 8 + tig * 2;
                    if (c     < Nreal) m = fmaxf(m, acc[i][j][h2 * 2 + 0]);
                    if (c + 1 < Nreal) m = fmaxf(m, acc[i][j][h2 * 2 + 1]);
                }
                float s = 0.f;
                #pragma unroll
                for (int j = 0; j < 4; j++) {
                    int c = col0 + wc + j * 8 + tig * 2;
                    if (c     < Nreal) s += __expf(acc[i][j][h2 * 2 + 0] - m);
                    if (c + 1 < Nreal) s += __expf(acc[i][j][h2 * 2 + 1] - m);
                }
                #pragma unroll
                for (int o = 1; o <= 2; o <<= 1) {
                    float mo = __shfl_xor_sync(0xffffffffu, m, o);
                    float so = __shfl_xor_sync(0xffffffffu, s, o);
                    float M = fmaxf(m, mo);
                    s = s * __expf(m - M) + so * __expf(mo - M);
                    m = M;
                }
                if (tig == 0) {
                    int rr = wr + i * 16 + gid + h2 * 8;
                    sls[rr * 4 + (wid & 3)] = make_float2(m, s);
                }
            }
        __syncthreads();
        if (tid < 128) {
            float m = -1e30f, s = 0.f;
            #pragma unroll
            for (int g = 0; g < 4; g++) {
                float2 p = sls[tid * 4 + g];
                float M = fmaxf(m, p.x);
                s = s * __expf(m - M) + p.y * __expf(p.x - M);
                m = M;
            }
            size_t idx = (size_t)(row0 + tid) * gx + blockIdx.x;
            lsem[idx] = m;
            lses[idx] = s;
        }
    }
}

// ---------------- loss reduce --------------------------------------------------
__global__ void zero_loss_kernel() { g_loss = 0.f; }

__global__ void loss_reduce_kernel(const float* __restrict__ logits,
                                   const int* __restrict__ target, int gx) {
    int row = blockIdx.x, tid = threadIdx.x;   // 128 threads
    float m = -1e30f, s = 0.f;
    for (int i = tid; i < gx; i += 128) {
        size_t idx = (size_t)row * gx + i;
        float pm = g_lsem[idx], ps = g_lses[idx];
        float M = fmaxf(m, pm);
        s = s * __expf(m - M) + ps * __expf(pm - M);
        m = M;
    }
    #pragma unroll
    for (int o = 16; o; o >>= 1) {
        float mo = __shfl_xor_sync(0xffffffffu, m, o);
        float so = __shfl_xor_sync(0xffffffffu, s, o);
        float M = fmaxf(m, mo);
        s = s * __expf(m - M) + so * __expf(mo - M);
        m = M;
    }
    __shared__ float rm[4], rs[4];
    if ((tid & 31) == 0) { rm[tid >> 5] = m; rs[tid >> 5] = s; }
    __syncthreads();
    if (tid == 0) {
        float M = fmaxf(fmaxf(rm[0], rm[1]), fmaxf(rm[2], rm[3]));
        float S = 0.f;
        #pragma unroll
        for (int i = 0; i < 4; i++) S += rs[i] * __expf(rm[i] - M);
        float lse = M + logf(S);
        atomicAdd(&g_loss, lse - logits[(size_t)row * VV + target[row]]);
    }
}

__global__ void finalize_loss_kernel(float* __restrict__ out) {
    out[(size_t)BT * VV] = g_loss * (1.0f / BT);
}

// ---------------- fused flash attention ---------------------------------------
#define FBQ 128
#define FBS 64
#define KLD 68
#define VLD 72
#define PLD 136
#define FSMEM ((FBS*KLD + FBS*VLD + FBS*PLD) * 4)

__global__ __launch_bounds__(256, 1)
void flash_kernel(const float* __restrict__ qkv, __half* __restrict__ outp) {
    extern __shared__ float fsm[];
    float* Ks = fsm;
    float* Vs = fsm + FBS * KLD;
    float* Ps = fsm + FBS * (KLD + VLD);

    int tid = threadIdx.x;
    int lane = tid & 31, gid = lane >> 2, tig = lane & 3;
    int wid = tid >> 5;
    int wrow = wid * 16;
    int q0 = (gridDim.x - 1 - blockIdx.x) * FBQ;
    int z = blockIdx.y;
    int b = z >> 3, h = z & 7;
    const float* qbase = qkv + (size_t)b * TT * (3 * CC) + h * HDIM;
    const float* kbase = qbase + CC;
    const float* vbase = qbase + 2 * CC;

    uint32_t aQ[8][4];
    {
        int t0 = q0 + wrow + gid;
        const float* q0p = qbase + (size_t)t0 * (3 * CC);
        const float* q1p = q0p + 8 * (3 * CC);
        #pragma unroll
        for (int ks = 0; ks < 8; ks++) {
            aQ[ks][0] = __float_as_uint(q0p[ks * 8 + tig]);
            aQ[ks][1] = __float_as_uint(q1p[ks * 8 + tig]);
            aQ[ks][2] = __float_as_uint(q0p[ks * 8 + tig + 4]);
            aQ[ks][3] = __float_as_uint(q1p[ks * 8 + tig + 4]);
        }
    }
    float oAcc[8][4];
    #pragma unroll
    for (int j = 0; j < 8; j++)
        #pragma unroll
        for (int q = 0; q < 4; q++) oAcc[j][q] = 0.f;
    float m0 = -1e30f, m1 = -1e30f, l0 = 0.f, l1 = 0.f;
    int t0g = q0 + wrow + gid, t1g = t0g + 8;
    int nTiles = q0 / FBS + 2;

    for (int it = 0; it < nTiles; it++) {
        int s0 = it * FBS;
        __syncthreads();
        #pragma unroll
        for (int i = 0; i < 4; i++) {
            int f4 = tid + i * 256;
            int r = f4 >> 4, kc = (f4 & 15) << 2;
            float4 kv = *reinterpret_cast<const float4*>(
                kbase + (size_t)(s0 + r) * (3 * CC) + kc);
            *reinterpret_cast<float4*>(Ks + r * KLD + kc) = kv;
            float4 vv = *reinterpret_cast<const float4*>(
                vbase + (size_t)(s0 + r) * (3 * CC) + kc);
            *reinterpret_cast<float4*>(Vs + r * VLD + kc) = vv;
        }
        __syncthreads();

        float sAcc[8][4];
        #pragma unroll
        for (int j = 0; j < 8; j++)
            #pragma unroll
            for (int q = 0; q < 4; q++) sAcc[j][q] = 0.f;
        #pragma unroll
        for (int ks = 0; ks < 8; ks++) {
            int kb = ks * 8;
            #pragma unroll
            for (int j = 0; j < 8; j++) {
                int n = j * 8 + gid;
                uint32_t bb[2];
                bb[0] = __float_as_uint(Ks[n * KLD + kb + tig]);
                bb[1] = __float_as_uint(Ks[n * KLD + kb + tig + 4]);
                mma8(sAcc[j], aQ[ks], bb);
            }
        }
        #pragma unroll
        for (int j = 0; j < 8; j++) {
            int sb = s0 + j * 8 + tig * 2;
            #pragma unroll
            for (int q = 0; q < 4; q++) {
                float v = sAcc[j][q] * 0.125f;
                int s_g = sb + (q & 1);
                int t_g = (q < 2) ? t0g : t1g;
                sAcc[j][q] = (s_g > t_g) ? -1e30f : v;
            }
        }
        float rm0 = -1e30f, rm1 = -1e30f;
        #pragma unroll
        for (int j = 0; j < 8; j++) {
            rm0 = fmaxf(rm0, fmaxf(sAcc[j][0], sAcc[j][1]));
            rm1 = fmaxf(rm1, fmaxf(sAcc[j][2], sAcc[j][3]));
        }
        #pragma unroll
        for (int o = 1; o <= 2; o <<= 1) {
            rm0 = fmaxf(rm0, __shfl_xor_sync(0xffffffffu, rm0, o));
            rm1 = fmaxf(rm1, __shfl_xor_sync(0xffffffffu, rm1, o));
        }
        float nm0 = fmaxf(m0, rm0), nm1 = fmaxf(m1, rm1);
        float a0 = __expf(m0 - nm0), a1 = __expf(m1 - nm1);
        float rs0 = 0.f, rs1 = 0.f;
        #pragma unroll
        for (int j = 0; j < 8; j++) {
            int sb = (j * 8 + tig * 2) * PLD;
            float p0 = __expf(sAcc[j][0] - nm0);
            float p1 = __expf(sAcc[j][1] - nm0);
            float p2 = __expf(sAcc[j][2] - nm1);
            float p3 = __expf(sAcc[j][3] - nm1);
            rs0 += p0 + p1; rs1 += p2 + p3;
            int tc0 = wrow + gid, tc1 = tc0 + 8;
            Ps[sb       + tc0] = tf32r(p0);
            Ps[sb + PLD + tc0] = tf32r(p1);
            Ps[sb       + tc1] = tf32r(p2);
            Ps[sb + PLD + tc1] = tf32r(p3);
        }
        #pragma unroll
        for (int o = 1; o <= 2; o <<= 1) {
            rs0 += __shfl_xor_sync(0xffffffffu, rs0, o);
            rs1 += __shfl_xor_sync(0xffffffffu, rs1, o);
        }
        l0 = l0 * a0 + rs0;
        l1 = l1 * a1 + rs1;
        m0 = nm0; m1 = nm1;
        #pragma unroll
        for (int j = 0; j < 8; j++) {
            oAcc[j][0] *= a0; oAcc[j][1] *= a0;
            oAcc[j][2] *= a1; oAcc[j][3] *= a1;
        }
        __syncwarp();
        #pragma unroll
        for (int ks = 0; ks < 8; ks++) {
            int kb = ks * 8;
            uint32_t aP[4];
            int mr = wrow + gid;
            aP[0] = __float_as_uint(Ps[(kb + tig    ) * PLD + mr    ]);
            aP[1] = __float_as_uint(Ps[(kb + tig    ) * PLD + mr + 8]);
            aP[2] = __float_as_uint(Ps[(kb + tig + 4) * PLD + mr    ]);
            aP[3] = __float_as_uint(Ps[(kb + tig + 4) * PLD + mr + 8]);
            #pragma unroll
            for (int j = 0; j < 8; j++) {
                int n = j * 8 + gid;
                uint32_t bb[2];
                bb[0] = __float_as_uint(Vs[(kb + tig    ) * VLD + n]);
                bb[1] = __float_as_uint(Vs[(kb + tig + 4) * VLD + n]);
                mma8(oAcc[j], aP, bb);
            }
        }
    }
    float inv0 = 1.f / l0, inv1 = 1.f / l1;
    __half* o0 = outp + (size_t)(b * TT + t0g) * CC + h * HDIM;
    __half* o1 = outp + (size_t)(b * TT + t1g) * CC + h * HDIM;
    #pragma unroll
    for (int j = 0; j < 8; j++) {
        int d = j * 8 + tig * 2;
        o0[d]     = __float2half_rn(oAcc[j][0] * inv0);
        o0[d + 1] = __float2half_rn(oAcc[j][1] * inv0);
        o1[d]     = __float2half_rn(oAcc[j][2] * inv1);
        o1[d + 1] = __float2half_rn(oAcc[j][3] * inv1);
    }
}

// ---------------- launch ------------------------------------------------------
extern "C" void kernel_launch(void* const* d_in, const int* in_sizes, int n_in,
                              void* d_out, int out_size) {
    const int*   x      = (const int*)  d_in[0];
    const int*   target = (const int*)  d_in[1];
    const float* tok    = (const float*)d_in[2];
    const float* pos    = (const float*)d_in[3];
    const float* ln1s   = (const float*)d_in[4];
    const float* ln1b   = (const float*)d_in[5];
    const float* wq     = (const float*)d_in[6];
    const float* wk     = (const float*)d_in[7];
    const float* wv     = (const float*)d_in[8];
    const float* wproj  = (const float*)d_in[9];
    const float* bproj  = (const float*)d_in[10];
    const float* ln2s   = (const float*)d_in[11];
    const float* ln2b   = (const float*)d_in[12];
    const float* wff1   = (const float*)d_in[13];
    const float* bff1   = (const float*)d_in[14];
    const float* wff2   = (const float*)d_in[15];
    const float* bff2   = (const float*)d_in[16];
    const float* lnfs   = (const float*)d_in[17];
    const float* lnfb   = (const float*)d_in[18];
    const float* lmw    = (const float*)d_in[19];
    const float* lmb    = (const float*)d_in[20];
    float* out = (float*)d_out;

    float  *p_h, *p_qkv, *p_lsem, *p_lses;
    __half *p_ainh, *p_attnh, *p_ffh, *p_wqkvT, *p_wpT, *p_w1T, *p_w2T, *p_lmwT;
    cudaGetSymbolAddress((void**)&p_h,     g_h);
    cudaGetSymbolAddress((void**)&p_qkv,   g_qkv);
    cudaGetSymbolAddress((void**)&p_lsem,  g_lsem);
    cudaGetSymbolAddress((void**)&p_lses,  g_lses);
    cudaGetSymbolAddress((void**)&p_ainh,  g_ainh);
    cudaGetSymbolAddress((void**)&p_attnh, g_attnh);
    cudaGetSymbolAddress((void**)&p_ffh,   g_ffh);
    cudaGetSymbolAddress((void**)&p_wqkvT, g_wqkvT);
    cudaGetSymbolAddress((void**)&p_wpT,   g_wpT);
    cudaGetSymbolAddress((void**)&p_w1T,   g_w1T);
    cudaGetSymbolAddress((void**)&p_w2T,   g_w2T);
    cudaGetSymbolAddress((void**)&p_lmwT,  g_lmwT);

    static int attr_done = 0;
    if (!attr_done) {
        cudaFuncSetAttribute(flash_kernel,
                             cudaFuncAttributeMaxDynamicSharedMemorySize, FSMEM);
        cudaFuncSetAttribute(gemm_fp16_kernel,
                             cudaFuncAttributeMaxDynamicSharedMemorySize, HSMEM);
        attr_done = 1;
    }

    prep_kernel<<<T_ALL, dim3(32, 8)>>>(wq, wk, wv, wproj, wff1, wff2, lmw);
    embed_kernel<<<(BT * CC + 255) / 256, 256>>>(x, tok, pos);

    dim3 gQKV(12, 32), gC2(4, 32), gFF(16, 32), gV(GXV, 32);
    dim3 gFA(TT / FBQ, BHZ);

    for (int l = 0; l < LLAY; l++) {
        ln_kernel<<<BT, 256>>>(p_h, ln1s + l * CC, ln1b + l * CC, p_ainh);
        gemm_fp16_kernel<<<gQKV, 256, HSMEM>>>(
            p_ainh, p_wqkvT + (size_t)l * 3 * CC * CC, p_qkv, nullptr,
            3 * CC, CC, nullptr, nullptr, 0, 1, nullptr, nullptr, 0);
        flash_kernel<<<gFA, 256, FSMEM>>>(p_qkv, p_attnh);
        gemm_fp16_kernel<<<gC2, 256, HSMEM>>>(
            p_attnh, p_wpT + (size_t)l * CC * CC, p_h, nullptr,
            CC, CC, bproj + l * CC, p_h, 0, 0, nullptr, nullptr, 0);
        ln_kernel<<<BT, 256>>>(p_h, ln2s + l * CC, ln2b + l * CC, p_ainh);
        gemm_fp16_kernel<<<gFF, 256, HSMEM>>>(
            p_ainh, p_w1T + (size_t)l * FFD * CC, nullptr, p_ffh,
            FFD, CC, bff1 + l * FFD, nullptr, 1, 0, nullptr, nullptr, 0);
        gemm_fp16_kernel<<<gC2, 256, HSMEM>>>(
            p_ffh, p_w2T + (size_t)l * CC * FFD, p_h, nullptr,
            CC, FFD, bff2 + l * CC, p_h, 0, 0, nullptr, nullptr, 0);
    }

    ln_kernel<<<BT, 256>>>(p_h, lnfs, lnfb, p_ainh);
    gemm_fp16_kernel<<<gV, 256, HSMEM>>>(
        p_ainh, p_lmwT, out, nullptr, VV, CC, lmb, nullptr, 0, 0,
        p_lsem, p_lses, GXV);

    if ((long long)out_size > (long long)BT * VV) {
        zero_loss_kernel<<<1, 1>>>();
        loss_reduce_kernel<<<BT, 128>>>(out, target, GXV);
        finalize_loss_kernel<<<1, 1>>>(out);
    }
}

// round 13
// speedup vs baseline: 1.5824x; 1.5824x over previous
#include <cuda_runtime.h>
#include <cuda_fp16.h>
#include <math.h>
#include <stdint.h>

#define BATCH 2
#define TT    2048
#define BT    4096
#define CC    512
#define HH    8
#define HDIM  64
#define LLAY  4
#define VV    50257
#define VPAD  50304               // multiple of 128
#define FFD   2048
#define LNEPS 1e-5f
#define BHZ   16
#define GXV   (VPAD/128)          // 393 LM-head col tiles

// ---------------- scratch -----------------------------------------------------
__device__ float  g_h    [BT*CC];
__device__ __half g_ainh [BT*CC];
__device__ float  g_qkv  [BT*3*CC];
__device__ __half g_attnh[BT*CC];
__device__ __half g_ffh  [(size_t)BT*FFD];
__device__ __half g_wqkvT[(size_t)LLAY*3*CC*CC];
__device__ __half g_wpT  [(size_t)LLAY*CC*CC];
__device__ __half g_w1T  [(size_t)LLAY*FFD*CC];
__device__ __half g_w2T  [(size_t)LLAY*CC*FFD];
__device__ __half g_lmwT [(size_t)VPAD*CC];
__device__ float  g_lsem [(size_t)BT*400];
__device__ float  g_lses [(size_t)BT*400];
__device__ float  g_loss;

// ---------------- helpers ------------------------------------------------------
__device__ __forceinline__ float warpSum(float v) {
    #pragma unroll
    for (int o = 16; o; o >>= 1) v += __shfl_xor_sync(0xffffffffu, v, o);
    return v;
}
__device__ __forceinline__ float tf32r(float x) {
    uint32_t u;
    asm("cvt.rna.tf32.f32 %0, %1;" : "=r"(u) : "f"(x));
    return __uint_as_float(u);
}
__device__ __forceinline__ void mma8(float* c, const uint32_t* a, const uint32_t* b) {
    asm volatile(
        "mma.sync.aligned.m16n8k8.row.col.f32.tf32.tf32.f32 "
        "{%0,%1,%2,%3}, {%4,%5,%6,%7}, {%8,%9}, {%0,%1,%2,%3};"
        : "+f"(c[0]), "+f"(c[1]), "+f"(c[2]), "+f"(c[3])
        : "r"(a[0]), "r"(a[1]), "r"(a[2]), "r"(a[3]), "r"(b[0]), "r"(b[1]));
}
__device__ __forceinline__ void mma16(float* c, const uint32_t* a, const uint32_t* b) {
    asm volatile(
        "mma.sync.aligned.m16n8k16.row.col.f32.f16.f16.f32 "
        "{%0,%1,%2,%3}, {%4,%5,%6,%7}, {%8,%9}, {%0,%1,%2,%3};"
        : "+f"(c[0]), "+f"(c[1]), "+f"(c[2]), "+f"(c[3])
        : "r"(a[0]), "r"(a[1]), "r"(a[2]), "r"(a[3]), "r"(b[0]), "r"(b[1]));
}
__device__ __forceinline__ uint32_t sptr(const void* p) {
    return (uint32_t)__cvta_generic_to_shared(p);
}
#define CP_ASYNC16(d, s) \
    asm volatile("cp.async.ca.shared.global [%0], [%1], 16;\n" :: "r"(d), "l"(s))
#define CP_COMMIT() asm volatile("cp.async.commit_group;\n" ::: "memory")
#define CP_WAIT1()  asm volatile("cp.async.wait_group 1;\n"  ::: "memory")

// ---------------- fused weight prep (single launch) ---------------------------
#define T_QKV (48*16*LLAY)
#define T_WP  (16*16*LLAY)
#define T_W1  (64*16*LLAY)
#define T_W2  (16*64*LLAY)
#define T_LMW ((VPAD/32)*16)
#define T_ALL (T_QKV+T_WP+T_W1+T_W2+T_LMW)

__device__ __forceinline__ void trans_tile(__half* dst, const float* src,
                                           int R, int Creal, int xt, int yt,
                                           float (*t)[33], int tx, int ty) {
    int c0 = xt * 32, r0 = yt * 32;
    #pragma unroll
    for (int i = 0; i < 32; i += 8) {
        int c = c0 + tx;
        t[tx][ty + i] = (c < Creal) ? src[(size_t)(r0 + ty + i) * Creal + c] : 0.f;
    }
    __syncthreads();
    #pragma unroll
    for (int i = 0; i < 32; i += 8)
        dst[(size_t)(c0 + ty + i) * R + r0 + tx] = __float2half_rn(t[ty + i][tx]);
}

__global__ void prep_kernel(const float* __restrict__ wq, const float* __restrict__ wk,
                            const float* __restrict__ wv, const float* __restrict__ wproj,
                            const float* __restrict__ wff1, const float* __restrict__ wff2,
                            const float* __restrict__ lmw) {
    __shared__ float t[32][33];
    int tx = threadIdx.x, ty = threadIdx.y;
    int bid = blockIdx.x;
    if (bid < T_QKV) {
        int l = bid / (48 * 16), rem = bid % (48 * 16);
        int xt = rem % 48, yt = rem / 48;
        int j0 = xt * 32, c0 = yt * 32;
        int which = j0 >> 9, h = (j0 & 511) >> 6, d0 = j0 & 63;
        const float* w = (which == 0) ? wq : (which == 1) ? wk : wv;
        const float* s = w + (((size_t)l * HH + h) * CC) * HDIM;
        #pragma unroll
        for (int i = 0; i < 32; i += 8)
            t[tx][ty + i] = s[(size_t)(c0 + ty + i) * HDIM + d0 + tx];
        __syncthreads();
        __half* d = g_wqkvT + ((size_t)l * (3 * CC) + j0) * CC + c0;
        #pragma unroll
        for (int i = 0; i < 32; i += 8)
            d[(size_t)(ty + i) * CC + tx] = __float2half_rn(t[ty + i][tx]);
        return;
    }
    bid -= T_QKV;
    if (bid < T_WP) {
        int l = bid / 256, rem = bid % 256;
        trans_tile(g_wpT + (size_t)l * CC * CC, wproj + (size_t)l * CC * CC,
                   CC, CC, rem % 16, rem / 16, t, tx, ty);
        return;
    }
    bid -= T_WP;
    if (bid < T_W1) {
        int l = bid / 1024, rem = bid % 1024;
        trans_tile(g_w1T + (size_t)l * FFD * CC, wff1 + (size_t)l * CC * FFD,
                   CC, FFD, rem % 64, rem / 64, t, tx, ty);
        return;
    }
    bid -= T_W1;
    if (bid < T_W2) {
        int l = bid / 1024, rem = bid % 1024;
        trans_tile(g_w2T + (size_t)l * CC * FFD, wff2 + (size_t)l * FFD * CC,
                   FFD, CC, rem % 16, rem / 16, t, tx, ty);
        return;
    }
    bid -= T_W2;
    trans_tile(g_lmwT, lmw, CC, VV, bid % (VPAD / 32), bid / (VPAD / 32), t, tx, ty);
}

// ---------------- embedding / layernorm ---------------------------------------
__global__ void embed_kernel(const int* __restrict__ x, const float* __restrict__ tok,
                             const float* __restrict__ pos) {
    int i = blockIdx.x * blockDim.x + threadIdx.x;
    if (i >= BT * CC) return;
    int c = i % CC, bt = i / CC, t = bt % TT;
    g_h[i] = tok[(size_t)x[bt] * CC + c] + pos[(size_t)t * CC + c];
}

__global__ void ln_kernel(const float* __restrict__ in, const float* __restrict__ sc,
                          const float* __restrict__ bi, __half* __restrict__ out) {
    int row = blockIdx.x, tid = threadIdx.x;
    const float* r = in + (size_t)row * CC;
    float a = r[tid], b = r[tid + 256];
    float s = a + b, q = a * a + b * b;
    s = warpSum(s); q = warpSum(q);
    __shared__ float rs[8], rq[8];
    if ((tid & 31) == 0) { rs[tid >> 5] = s; rq[tid >> 5] = q; }
    __syncthreads();
    __shared__ float s_mean, s_rstd;
    if (tid == 0) {
        float S = 0.f, Q = 0.f;
        #pragma unroll
        for (int i = 0; i < 8; i++) { S += rs[i]; Q += rq[i]; }
        float m = S * (1.0f / CC);
        s_mean = m; s_rstd = rsqrtf(Q * (1.0f / CC) - m * m + LNEPS);
    }
    __syncthreads();
    float m = s_mean, rstd = s_rstd;
    __half* o = out + (size_t)row * CC;
    o[tid]       = __float2half_rn((a - m) * rstd * sc[tid]       + bi[tid]);
    o[tid + 256] = __float2half_rn((b - m) * rstd * sc[tid + 256] + bi[tid + 256]);
}

// ---------------- fp16 GEMM: C[M,N] = A[M,K] @ Bt[N,K]^T ----------------------
// 128x128 tile, BK=32 halves, 256 thr (8 warps 2x4, 64x32 each), 3-stage.
// __launch_bounds__(256,2): 128 regs -> NO accumulator spills (R11 bug).
#define ALD 40
#define STGB 20480
#define HSMEM (3*STGB)

__global__ __launch_bounds__(256, 2)
void gemm_fp16_kernel(const __half* __restrict__ A, const __half* __restrict__ Bt,
                      float* __restrict__ Cout, __half* __restrict__ CoutH,
                      int Nreal, int K,
                      const float* __restrict__ bias, const float* __restrict__ res,
                      int relu, int rnd,
                      float* __restrict__ lsem, float* __restrict__ lses, int gx) {
    extern __shared__ __align__(16) char hsm[];
    int tid = threadIdx.x;
    int row0 = blockIdx.y << 7, col0 = blockIdx.x << 7;
    int lane = tid & 31, gid = lane >> 2, tig = lane & 3;
    int wid = tid >> 5;
    int wr = (wid >> 2) * 64;
    int wc = (wid & 3) * 32;

    float acc[4][4][4];
    #pragma unroll
    for (int i = 0; i < 4; i++)
        #pragma unroll
        for (int j = 0; j < 4; j++)
            #pragma unroll
            for (int q = 0; q < 4; q++) acc[i][j][q] = 0.f;

    const __half* Ab = A + (size_t)row0 * K;
    const __half* Bb = Bt + (size_t)col0 * K;
    int r0 = tid >> 2, c0 = tid & 3;
    int r1 = (tid + 256) >> 2, c1 = (tid + 256) & 3;

    #define LOAD_STAGE(st, k0)                                                 \
        do {                                                                   \
            uint32_t as = sptr(hsm) + (st) * STGB;                             \
            uint32_t bs = as + 10240;                                          \
            CP_ASYNC16(as + r0 * 80 + c0 * 16, Ab + (size_t)r0 * K + (k0) + c0 * 8); \
            CP_ASYNC16(as + r1 * 80 + c1 * 16, Ab + (size_t)r1 * K + (k0) + c1 * 8); \
            CP_ASYNC16(bs + r0 * 80 + c0 * 16, Bb + (size_t)r0 * K + (k0) + c0 * 8); \
            CP_ASYNC16(bs + r1 * 80 + c1 * 16, Bb + (size_t)r1 * K + (k0) + c1 * 8); \
        } while (0)

    int ntiles = K >> 5;
    LOAD_STAGE(0, 0);  CP_COMMIT();
    if (ntiles > 1) LOAD_STAGE(1, 32);
    CP_COMMIT();

    int st = 0;
    for (int it = 0; it < ntiles; it++) {
        CP_WAIT1();
        __syncthreads();
        int nx = it + 2;
        int stn = st + 2; if (stn >= 3) stn -= 3;
        if (nx < ntiles) LOAD_STAGE(stn, nx << 5);
        CP_COMMIT();

        const __half* as = (const __half*)(hsm + st * STGB);
        const __half* bs = as + 5120;
        #pragma unroll
        for (int ks = 0; ks < 2; ks++) {
            int kb = ks << 4;
            uint32_t af[4][4], bf[4][2];
            #pragma unroll
            for (int i = 0; i < 4; i++) {
                int m = wr + i * 16 + gid;
                af[i][0] = *(const uint32_t*)&as[(m    ) * ALD + kb + 2 * tig    ];
                af[i][1] = *(const uint32_t*)&as[(m + 8) * ALD + kb + 2 * tig    ];
                af[i][2] = *(const uint32_t*)&as[(m    ) * ALD + kb + 2 * tig + 8];
                af[i][3] = *(const uint32_t*)&as[(m + 8) * ALD + kb + 2 * tig + 8];
            }
            #pragma unroll
            for (int j = 0; j < 4; j++) {
                int n = wc + j * 8 + gid;
                bf[j][0] = *(const uint32_t*)&bs[n * ALD + kb + 2 * tig    ];
                bf[j][1] = *(const uint32_t*)&bs[n * ALD + kb + 2 * tig + 8];
            }
            #pragma unroll
            for (int i = 0; i < 4; i++)
                #pragma unroll
                for (int j = 0; j < 4; j++)
                    mma16(acc[i][j], af[i], bf[j]);
        }
        if (++st == 3) st = 0;
    }
    #undef LOAD_STAGE

    #pragma unroll
    for (int i = 0; i < 4; i++)
        #pragma unroll
        for (int j = 0; j < 4; j++) {
            int cc0 = col0 + wc + j * 8 + tig * 2;
            #pragma unroll
            for (int h2 = 0; h2 < 2; h2++) {
                int r = row0 + wr + i * 16 + gid + h2 * 8;
                float v0 = acc[i][j][h2 * 2 + 0];
                float v1 = acc[i][j][h2 * 2 + 1];
                if (cc0 < Nreal) {
                    if (bias) v0 += bias[cc0];
                    if (res)  v0 += res[(size_t)r * Nreal + cc0];
                    if (relu) v0 = fmaxf(v0, 0.f);
                    acc[i][j][h2 * 2 + 0] = v0;
                    if (CoutH) CoutH[(size_t)r * Nreal + cc0] = __float2half_rn(v0);
                    else       Cout [(size_t)r * Nreal + cc0] = rnd ? tf32r(v0) : v0;
                }
                if (cc0 + 1 < Nreal) {
                    if (bias) v1 += bias[cc0 + 1];
                    if (res)  v1 += res[(size_t)r * Nreal + cc0 + 1];
                    if (relu) v1 = fmaxf(v1, 0.f);
                    acc[i][j][h2 * 2 + 1] = v1;
                    if (CoutH) CoutH[(size_t)r * Nreal + cc0 + 1] = __float2half_rn(v1);
                    else       Cout [(size_t)r * Nreal + cc0 + 1] = rnd ? tf32r(v1) : v1;
                }
            }
        }

    // fused partial logsumexp over this CTA's 128 columns (LM head only)
    if (lsem) {
        float2* sls = (float2*)hsm;
        __syncthreads();
        #pragma unroll
        for (int i = 0; i < 4; i++)
            #pragma unroll
            for (int h2 = 0; h2 < 2; h2++) {
                float m = -1e30f;
                #pragma unroll
                for (int j = 0; j < 4; j++) {
                    int c = col0 + wc + j * 8 + tig * 2;
                    if (c     < Nreal) m = fmaxf(m, acc[i][j][h2 * 2 + 0]);
                    if (c + 1 < Nreal) m = fmaxf(m, acc[i][j][h2 * 2 + 1]);
                }
                float s = 0.f;
                #pragma unroll
                for (int j = 0; j < 4; j++) {
                    int c = col0 + wc + j * 8 + tig * 2;
                    if (c     < Nreal) s += __expf(acc[i][j][h2 * 2 + 0] - m);
                    if (c + 1 < Nreal) s += __expf(acc[i][j][h2 * 2 + 1] - m);
                }
                #pragma unroll
                for (int o = 1; o <= 2; o <<= 1) {
                    float mo = __shfl_xor_sync(0xffffffffu, m, o);
                    float so = __shfl_xor_sync(0xffffffffu, s, o);
                    float M = fmaxf(m, mo);
                    s = s * __expf(m - M) + so * __expf(mo - M);
                    m = M;
                }
                if (tig == 0) {
                    int rr = wr + i * 16 + gid + h2 * 8;
                    sls[rr * 4 + (wid & 3)] = make_float2(m, s);
                }
            }
        __syncthreads();
        if (tid < 128) {
            float m = -1e30f, s = 0.f;
            #pragma unroll
            for (int g = 0; g < 4; g++) {
                float2 p = sls[tid * 4 + g];
                float M = fmaxf(m, p.x);
                s = s * __expf(m - M) + p.y * __expf(p.x - M);
                m = M;
            }
            size_t idx = (size_t)(row0 + tid) * gx + blockIdx.x;
            lsem[idx] = m;
            lses[idx] = s;
        }
    }
}

// ---------------- loss reduce --------------------------------------------------
__global__ void zero_loss_kernel() { g_loss = 0.f; }

__global__ void loss_reduce_kernel(const float* __restrict__ logits,
                                   const int* __restrict__ target, int gx) {
    int row = blockIdx.x, tid = threadIdx.x;   // 128 threads
    float m = -1e30f, s = 0.f;
    for (int i = tid; i < gx; i += 128) {
        size_t idx = (size_t)row * gx + i;
        float pm = g_lsem[idx], ps = g_lses[idx];
        float M = fmaxf(m, pm);
        s = s * __expf(m - M) + ps * __expf(pm - M);
        m = M;
    }
    #pragma unroll
    for (int o = 16; o; o >>= 1) {
        float mo = __shfl_xor_sync(0xffffffffu, m, o);
        float so = __shfl_xor_sync(0xffffffffu, s, o);
        float M = fmaxf(m, mo);
        s = s * __expf(m - M) + so * __expf(mo - M);
        m = M;
    }
    __shared__ float rm[4], rs[4];
    if ((tid & 31) == 0) { rm[tid >> 5] = m; rs[tid >> 5] = s; }
    __syncthreads();
    if (tid == 0) {
        float M = fmaxf(fmaxf(rm[0], rm[1]), fmaxf(rm[2], rm[3]));
        float S = 0.f;
        #pragma unroll
        for (int i = 0; i < 4; i++) S += rs[i] * __expf(rm[i] - M);
        float lse = M + logf(S);
        atomicAdd(&g_loss, lse - logits[(size_t)row * VV + target[row]]);
    }
}

__global__ void finalize_loss_kernel(float* __restrict__ out) {
    out[(size_t)BT * VV] = g_loss * (1.0f / BT);
}

// ---------------- fused flash attention ---------------------------------------
#define FBQ 128
#define FBS 64
#define KLD 68
#define VLD 72
#define PLD 136
#define FSMEM ((FBS*KLD + FBS*VLD + FBS*PLD) * 4)

__global__ __launch_bounds__(256, 1)
void flash_kernel(const float* __restrict__ qkv, __half* __restrict__ outp) {
    extern __shared__ float fsm[];
    float* Ks = fsm;
    float* Vs = fsm + FBS * KLD;
    float* Ps = fsm + FBS * (KLD + VLD);

    int tid = threadIdx.x;
    int lane = tid & 31, gid = lane >> 2, tig = lane & 3;
    int wid = tid >> 5;
    int wrow = wid * 16;
    int q0 = (gridDim.x - 1 - blockIdx.x) * FBQ;
    int z = blockIdx.y;
    int b = z >> 3, h = z & 7;
    const float* qbase = qkv + (size_t)b * TT * (3 * CC) + h * HDIM;
    const float* kbase = qbase + CC;
    const float* vbase = qbase + 2 * CC;

    uint32_t aQ[8][4];
    {
        int t0 = q0 + wrow + gid;
        const float* q0p = qbase + (size_t)t0 * (3 * CC);
        const float* q1p = q0p + 8 * (3 * CC);
        #pragma unroll
        for (int ks = 0; ks < 8; ks++) {
            aQ[ks][0] = __float_as_uint(q0p[ks * 8 + tig]);
            aQ[ks][1] = __float_as_uint(q1p[ks * 8 + tig]);
            aQ[ks][2] = __float_as_uint(q0p[ks * 8 + tig + 4]);
            aQ[ks][3] = __float_as_uint(q1p[ks * 8 + tig + 4]);
        }
    }
    float oAcc[8][4];
    #pragma unroll
    for (int j = 0; j < 8; j++)
        #pragma unroll
        for (int q = 0; q < 4; q++) oAcc[j][q] = 0.f;
    float m0 = -1e30f, m1 = -1e30f, l0 = 0.f, l1 = 0.f;
    int t0g = q0 + wrow + gid, t1g = t0g + 8;
    int nTiles = q0 / FBS + 2;

    for (int it = 0; it < nTiles; it++) {
        int s0 = it * FBS;
        __syncthreads();
        #pragma unroll
        for (int i = 0; i < 4; i++) {
            int f4 = tid + i * 256;
            int r = f4 >> 4, kc = (f4 & 15) << 2;
            float4 kv = *reinterpret_cast<const float4*>(
                kbase + (size_t)(s0 + r) * (3 * CC) + kc);
            *reinterpret_cast<float4*>(Ks + r * KLD + kc) = kv;
            float4 vv = *reinterpret_cast<const float4*>(
                vbase + (size_t)(s0 + r) * (3 * CC) + kc);
            *reinterpret_cast<float4*>(Vs + r * VLD + kc) = vv;
        }
        __syncthreads();

        float sAcc[8][4];
        #pragma unroll
        for (int j = 0; j < 8; j++)
            #pragma unroll
            for (int q = 0; q < 4; q++) sAcc[j][q] = 0.f;
        #pragma unroll
        for (int ks = 0; ks < 8; ks++) {
            int kb = ks * 8;
            #pragma unroll
            for (int j = 0; j < 8; j++) {
                int n = j * 8 + gid;
                uint32_t bb[2];
                bb[0] = __float_as_uint(Ks[n * KLD + kb + tig]);
                bb[1] = __float_as_uint(Ks[n * KLD + kb + tig + 4]);
                mma8(sAcc[j], aQ[ks], bb);
            }
        }
        #pragma unroll
        for (int j = 0; j < 8; j++) {
            int sb = s0 + j * 8 + tig * 2;
            #pragma unroll
            for (int q = 0; q < 4; q++) {
                float v = sAcc[j][q] * 0.125f;
                int s_g = sb + (q & 1);
                int t_g = (q < 2) ? t0g : t1g;
                sAcc[j][q] = (s_g > t_g) ? -1e30f : v;
            }
        }
        float rm0 = -1e30f, rm1 = -1e30f;
        #pragma unroll
        for (int j = 0; j < 8; j++) {
            rm0 = fmaxf(rm0, fmaxf(sAcc[j][0], sAcc[j][1]));
            rm1 = fmaxf(rm1, fmaxf(sAcc[j][2], sAcc[j][3]));
        }
        #pragma unroll
        for (int o = 1; o <= 2; o <<= 1) {
            rm0 = fmaxf(rm0, __shfl_xor_sync(0xffffffffu, rm0, o));
            rm1 = fmaxf(rm1, __shfl_xor_sync(0xffffffffu, rm1, o));
        }
        float nm0 = fmaxf(m0, rm0), nm1 = fmaxf(m1, rm1);
        float a0 = __expf(m0 - nm0), a1 = __expf(m1 - nm1);
        float rs0 = 0.f, rs1 = 0.f;
        #pragma unroll
        for (int j = 0; j < 8; j++) {
            int sb = (j * 8 + tig * 2) * PLD;
            float p0 = __expf(sAcc[j][0] - nm0);
            float p1 = __expf(sAcc[j][1] - nm0);
            float p2 = __expf(sAcc[j][2] - nm1);
            float p3 = __expf(sAcc[j][3] - nm1);
            rs0 += p0 + p1; rs1 += p2 + p3;
            int tc0 = wrow + gid, tc1 = tc0 + 8;
            Ps[sb       + tc0] = tf32r(p0);
            Ps[sb + PLD + tc0] = tf32r(p1);
            Ps[sb       + tc1] = tf32r(p2);
            Ps[sb + PLD + tc1] = tf32r(p3);
        }
        #pragma unroll
        for (int o = 1; o <= 2; o <<= 1) {
            rs0 += __shfl_xor_sync(0xffffffffu, rs0, o);
            rs1 += __shfl_xor_sync(0xffffffffu, rs1, o);
        }
        l0 = l0 * a0 + rs0;
        l1 = l1 * a1 + rs1;
        m0 = nm0; m1 = nm1;
        #pragma unroll
        for (int j = 0; j < 8; j++) {
            oAcc[j][0] *= a0; oAcc[j][1] *= a0;
            oAcc[j][2] *= a1; oAcc[j][3] *= a1;
        }
        __syncwarp();
        #pragma unroll
        for (int ks = 0; ks < 8; ks++) {
            int kb = ks * 8;
            uint32_t aP[4];
            int mr = wrow + gid;
            aP[0] = __float_as_uint(Ps[(kb + tig    ) * PLD + mr    ]);
            aP[1] = __float_as_uint(Ps[(kb + tig    ) * PLD + mr + 8]);
            aP[2] = __float_as_uint(Ps[(kb + tig + 4) * PLD + mr    ]);
            aP[3] = __float_as_uint(Ps[(kb + tig + 4) * PLD + mr + 8]);
            #pragma unroll
            for (int j = 0; j < 8; j++) {
                int n = j * 8 + gid;
                uint32_t bb[2];
                bb[0] = __float_as_uint(Vs[(kb + tig    ) * VLD + n]);
                bb[1] = __float_as_uint(Vs[(kb + tig + 4) * VLD + n]);
                mma8(oAcc[j], aP, bb);
            }
        }
    }
    float inv0 = 1.f / l0, inv1 = 1.f / l1;
    __half* o0 = outp + (size_t)(b * TT + t0g) * CC + h * HDIM;
    __half* o1 = outp + (size_t)(b * TT + t1g) * CC + h * HDIM;
    #pragma unroll
    for (int j = 0; j < 8; j++) {
        int d = j * 8 + tig * 2;
        o0[d]     = __float2half_rn(oAcc[j][0] * inv0);
        o0[d + 1] = __float2half_rn(oAcc[j][1] * inv0);
        o1[d]     = __float2half_rn(oAcc[j][2] * inv1);
        o1[d + 1] = __float2half_rn(oAcc[j][3] * inv1);
    }
}

// ---------------- launch ------------------------------------------------------
extern "C" void kernel_launch(void* const* d_in, const int* in_sizes, int n_in,
                              void* d_out, int out_size) {
    const int*   x      = (const int*)  d_in[0];
    const int*   target = (const int*)  d_in[1];
    const float* tok    = (const float*)d_in[2];
    const float* pos    = (const float*)d_in[3];
    const float* ln1s   = (const float*)d_in[4];
    const float* ln1b   = (const float*)d_in[5];
    const float* wq     = (const float*)d_in[6];
    const float* wk     = (const float*)d_in[7];
    const float* wv     = (const float*)d_in[8];
    const float* wproj  = (const float*)d_in[9];
    const float* bproj  = (const float*)d_in[10];
    const float* ln2s   = (const float*)d_in[11];
    const float* ln2b   = (const float*)d_in[12];
    const float* wff1   = (const float*)d_in[13];
    const float* bff1   = (const float*)d_in[14];
    const float* wff2   = (const float*)d_in[15];
    const float* bff2   = (const float*)d_in[16];
    const float* lnfs   = (const float*)d_in[17];
    const float* lnfb   = (const float*)d_in[18];
    const float* lmw    = (const float*)d_in[19];
    const float* lmb    = (const float*)d_in[20];
    float* out = (float*)d_out;

    float  *p_h, *p_qkv, *p_lsem, *p_lses;
    __half *p_ainh, *p_attnh, *p_ffh, *p_wqkvT, *p_wpT, *p_w1T, *p_w2T, *p_lmwT;
    cudaGetSymbolAddress((void**)&p_h,     g_h);
    cudaGetSymbolAddress((void**)&p_qkv,   g_qkv);
    cudaGetSymbolAddress((void**)&p_lsem,  g_lsem);
    cudaGetSymbolAddress((void**)&p_lses,  g_lses);
    cudaGetSymbolAddress((void**)&p_ainh,  g_ainh);
    cudaGetSymbolAddress((void**)&p_attnh, g_attnh);
    cudaGetSymbolAddress((void**)&p_ffh,   g_ffh);
    cudaGetSymbolAddress((void**)&p_wqkvT, g_wqkvT);
    cudaGetSymbolAddress((void**)&p_wpT,   g_wpT);
    cudaGetSymbolAddress((void**)&p_w1T,   g_w1T);
    cudaGetSymbolAddress((void**)&p_w2T,   g_w2T);
    cudaGetSymbolAddress((void**)&p_lmwT,  g_lmwT);

    static int attr_done = 0;
    if (!attr_done) {
        cudaFuncSetAttribute(flash_kernel,
                             cudaFuncAttributeMaxDynamicSharedMemorySize, FSMEM);
        cudaFuncSetAttribute(gemm_fp16_kernel,
                             cudaFuncAttributeMaxDynamicSharedMemorySize, HSMEM);
        attr_done = 1;
    }

    prep_kernel<<<T_ALL, dim3(32, 8)>>>(wq, wk, wv, wproj, wff1, wff2, lmw);
    embed_kernel<<<(BT * CC + 255) / 256, 256>>>(x, tok, pos);

    dim3 gQKV(12, 32), gC2(4, 32), gFF(16, 32), gV(GXV, 32);
    dim3 gFA(TT / FBQ, BHZ);

    for (int l = 0; l < LLAY; l++) {
        ln_kernel<<<BT, 256>>>(p_h, ln1s + l * CC, ln1b + l * CC, p_ainh);
        gemm_fp16_kernel<<<gQKV, 256, HSMEM>>>(
            p_ainh, p_wqkvT + (size_t)l * 3 * CC * CC, p_qkv, nullptr,
            3 * CC, CC, nullptr, nullptr, 0, 1, nullptr, nullptr, 0);
        flash_kernel<<<gFA, 256, FSMEM>>>(p_qkv, p_attnh);
        gemm_fp16_kernel<<<gC2, 256, HSMEM>>>(
            p_attnh, p_wpT + (size_t)l * CC * CC, p_h, nullptr,
            CC, CC, bproj + l * CC, p_h, 0, 0, nullptr, nullptr, 0);
        ln_kernel<<<BT, 256>>>(p_h, ln2s + l * CC, ln2b + l * CC, p_ainh);
        gemm_fp16_kernel<<<gFF, 256, HSMEM>>>(
            p_ainh, p_w1T + (size_t)l * FFD * CC, nullptr, p_ffh,
            FFD, CC, bff1 + l * FFD, nullptr, 1, 0, nullptr, nullptr, 0);
        gemm_fp16_kernel<<<gC2, 256, HSMEM>>>(
            p_ffh, p_w2T + (size_t)l * CC * FFD, p_h, nullptr,
            CC, FFD, bff2 + l * CC, p_h, 0, 0, nullptr, nullptr, 0);
    }

    ln_kernel<<<BT, 256>>>(p_h, lnfs, lnfb, p_ainh);
    gemm_fp16_kernel<<<gV, 256, HSMEM>>>(
        p_ainh, p_lmwT, out, nullptr, VV, CC, lmb, nullptr, 0, 0,
        p_lsem, p_lses, GXV);

    if ((long long)out_size > (long long)BT * VV) {
        zero_loss_kernel<<<1, 1>>>();
        loss_reduce_kernel<<<BT, 128>>>(out, target, GXV);
        finalize_loss_kernel<<<1, 1>>>(out);
    }
}

// round 14
// speedup vs baseline: 1.6825x; 1.0632x over previous
#include <cuda_runtime.h>
#include <cuda_fp16.h>
#include <math.h>
#include <stdint.h>

#define BATCH 2
#define TT    2048
#define BT    4096
#define CC    512
#define HH    8
#define HDIM  64
#define LLAY  4
#define VV    50257
#define VPAD  50304               // multiple of 128
#define FFD   2048
#define LNEPS 1e-5f
#define BHZ   16
#define GXV   (VPAD/128)          // 393 LM-head col tiles

// ---------------- scratch -----------------------------------------------------
__device__ float  g_h    [BT*CC];
__device__ __half g_ainh [BT*CC];
__device__ float  g_qkv  [BT*3*CC];
__device__ __half g_attnh[BT*CC];
__device__ __half g_ffh  [(size_t)BT*FFD];
__device__ __half g_wqkvT[(size_t)LLAY*3*CC*CC];
__device__ __half g_wpT  [(size_t)LLAY*CC*CC];
__device__ __half g_w1T  [(size_t)LLAY*FFD*CC];
__device__ __half g_w2T  [(size_t)LLAY*CC*FFD];
__device__ __half g_lmwT [(size_t)VPAD*CC];
__device__ float  g_lsem [(size_t)BT*400];
__device__ float  g_lses [(size_t)BT*400];
__device__ float  g_loss;

// ---------------- helpers ------------------------------------------------------
__device__ __forceinline__ float warpSum(float v) {
    #pragma unroll
    for (int o = 16; o; o >>= 1) v += __shfl_xor_sync(0xffffffffu, v, o);
    return v;
}
__device__ __forceinline__ float tf32r(float x) {
    uint32_t u;
    asm("cvt.rna.tf32.f32 %0, %1;" : "=r"(u) : "f"(x));
    return __uint_as_float(u);
}
__device__ __forceinline__ void mma8(float* c, const uint32_t* a, const uint32_t* b) {
    asm volatile(
        "mma.sync.aligned.m16n8k8.row.col.f32.tf32.tf32.f32 "
        "{%0,%1,%2,%3}, {%4,%5,%6,%7}, {%8,%9}, {%0,%1,%2,%3};"
        : "+f"(c[0]), "+f"(c[1]), "+f"(c[2]), "+f"(c[3])
        : "r"(a[0]), "r"(a[1]), "r"(a[2]), "r"(a[3]), "r"(b[0]), "r"(b[1]));
}
__device__ __forceinline__ void mma16(float* c, const uint32_t* a, const uint32_t* b) {
    asm volatile(
        "mma.sync.aligned.m16n8k16.row.col.f32.f16.f16.f32 "
        "{%0,%1,%2,%3}, {%4,%5,%6,%7}, {%8,%9}, {%0,%1,%2,%3};"
        : "+f"(c[0]), "+f"(c[1]), "+f"(c[2]), "+f"(c[3])
        : "r"(a[0]), "r"(a[1]), "r"(a[2]), "r"(a[3]), "r"(b[0]), "r"(b[1]));
}
#define LDSM4(r0, r1, r2, r3, addr) \
    asm volatile("ldmatrix.sync.aligned.m8n8.x4.shared.b16 {%0,%1,%2,%3}, [%4];" \
        : "=r"(r0), "=r"(r1), "=r"(r2), "=r"(r3) : "r"(addr))
__device__ __forceinline__ uint32_t sptr(const void* p) {
    return (uint32_t)__cvta_generic_to_shared(p);
}
#define CP_ASYNC16(d, s) \
    asm volatile("cp.async.ca.shared.global [%0], [%1], 16;\n" :: "r"(d), "l"(s))
#define CP_COMMIT() asm volatile("cp.async.commit_group;\n" ::: "memory")
#define CP_WAIT1()  asm volatile("cp.async.wait_group 1;\n"  ::: "memory")

// ---------------- fused weight prep (single launch) ---------------------------
#define T_QKV (48*16*LLAY)
#define T_WP  (16*16*LLAY)
#define T_W1  (64*16*LLAY)
#define T_W2  (16*64*LLAY)
#define T_LMW ((VPAD/32)*16)
#define T_ALL (T_QKV+T_WP+T_W1+T_W2+T_LMW)

__device__ __forceinline__ void trans_tile(__half* dst, const float* src,
                                           int R, int Creal, int xt, int yt,
                                           float (*t)[33], int tx, int ty) {
    int c0 = xt * 32, r0 = yt * 32;
    #pragma unroll
    for (int i = 0; i < 32; i += 8) {
        int c = c0 + tx;
        t[tx][ty + i] = (c < Creal) ? src[(size_t)(r0 + ty + i) * Creal + c] : 0.f;
    }
    __syncthreads();
    #pragma unroll
    for (int i = 0; i < 32; i += 8)
        dst[(size_t)(c0 + ty + i) * R + r0 + tx] = __float2half_rn(t[ty + i][tx]);
}

__global__ void prep_kernel(const float* __restrict__ wq, const float* __restrict__ wk,
                            const float* __restrict__ wv, const float* __restrict__ wproj,
                            const float* __restrict__ wff1, const float* __restrict__ wff2,
                            const float* __restrict__ lmw) {
    __shared__ float t[32][33];
    int tx = threadIdx.x, ty = threadIdx.y;
    int bid = blockIdx.x;
    if (bid < T_QKV) {
        int l = bid / (48 * 16), rem = bid % (48 * 16);
        int xt = rem % 48, yt = rem / 48;
        int j0 = xt * 32, c0 = yt * 32;
        int which = j0 >> 9, h = (j0 & 511) >> 6, d0 = j0 & 63;
        const float* w = (which == 0) ? wq : (which == 1) ? wk : wv;
        const float* s = w + (((size_t)l * HH + h) * CC) * HDIM;
        #pragma unroll
        for (int i = 0; i < 32; i += 8)
            t[tx][ty + i] = s[(size_t)(c0 + ty + i) * HDIM + d0 + tx];
        __syncthreads();
        __half* d = g_wqkvT + ((size_t)l * (3 * CC) + j0) * CC + c0;
        #pragma unroll
        for (int i = 0; i < 32; i += 8)
            d[(size_t)(ty + i) * CC + tx] = __float2half_rn(t[ty + i][tx]);
        return;
    }
    bid -= T_QKV;
    if (bid < T_WP) {
        int l = bid / 256, rem = bid % 256;
        trans_tile(g_wpT + (size_t)l * CC * CC, wproj + (size_t)l * CC * CC,
                   CC, CC, rem % 16, rem / 16, t, tx, ty);
        return;
    }
    bid -= T_WP;
    if (bid < T_W1) {
        int l = bid / 1024, rem = bid % 1024;
        trans_tile(g_w1T + (size_t)l * FFD * CC, wff1 + (size_t)l * CC * FFD,
                   CC, FFD, rem % 64, rem / 64, t, tx, ty);
        return;
    }
    bid -= T_W1;
    if (bid < T_W2) {
        int l = bid / 1024, rem = bid % 1024;
        trans_tile(g_w2T + (size_t)l * CC * FFD, wff2 + (size_t)l * FFD * CC,
                   FFD, CC, rem % 16, rem / 16, t, tx, ty);
        return;
    }
    bid -= T_W2;
    trans_tile(g_lmwT, lmw, CC, VV, bid % (VPAD / 32), bid / (VPAD / 32), t, tx, ty);
}

// ---------------- embedding / layernorm ---------------------------------------
__global__ void embed_kernel(const int* __restrict__ x, const float* __restrict__ tok,
                             const float* __restrict__ pos) {
    int i = blockIdx.x * blockDim.x + threadIdx.x;
    if (i >= BT * CC) return;
    int c = i % CC, bt = i / CC, t = bt % TT;
    g_h[i] = tok[(size_t)x[bt] * CC + c] + pos[(size_t)t * CC + c];
}

__global__ void ln_kernel(const float* __restrict__ in, const float* __restrict__ sc,
                          const float* __restrict__ bi, __half* __restrict__ out) {
    int row = blockIdx.x, tid = threadIdx.x;
    const float* r = in + (size_t)row * CC;
    float a = r[tid], b = r[tid + 256];
    float s = a + b, q = a * a + b * b;
    s = warpSum(s); q = warpSum(q);
    __shared__ float rs[8], rq[8];
    if ((tid & 31) == 0) { rs[tid >> 5] = s; rq[tid >> 5] = q; }
    __syncthreads();
    __shared__ float s_mean, s_rstd;
    if (tid == 0) {
        float S = 0.f, Q = 0.f;
        #pragma unroll
        for (int i = 0; i < 8; i++) { S += rs[i]; Q += rq[i]; }
        float m = S * (1.0f / CC);
        s_mean = m; s_rstd = rsqrtf(Q * (1.0f / CC) - m * m + LNEPS);
    }
    __syncthreads();
    float m = s_mean, rstd = s_rstd;
    __half* o = out + (size_t)row * CC;
    o[tid]       = __float2half_rn((a - m) * rstd * sc[tid]       + bi[tid]);
    o[tid + 256] = __float2half_rn((b - m) * rstd * sc[tid + 256] + bi[tid + 256]);
}

// ---------------- fp16 GEMM: C[M,N] = A[M,K] @ Bt[N,K]^T ----------------------
// 128x128 tile, BK=32 halves, 256 thr (8 warps 2x4, 64x32 each), 3-stage.
// ldmatrix.x4 fragment loads: 6 LDSM + 32 HMMA per k16-slice pair.
#define ALD 40
#define STGB 20480
#define HSMEM (3*STGB)

__global__ __launch_bounds__(256, 2)
void gemm_fp16_kernel(const __half* __restrict__ A, const __half* __restrict__ Bt,
                      float* __restrict__ Cout, __half* __restrict__ CoutH,
                      int Nreal, int K,
                      const float* __restrict__ bias, const float* __restrict__ res,
                      int relu, int rnd,
                      float* __restrict__ lsem, float* __restrict__ lses, int gx) {
    extern __shared__ __align__(16) char hsm[];
    int tid = threadIdx.x;
    int row0 = blockIdx.y << 7, col0 = blockIdx.x << 7;
    int lane = tid & 31, gid = lane >> 2, tig = lane & 3;
    int wid = tid >> 5;
    int wr = (wid >> 2) * 64;
    int wc = (wid & 3) * 32;

    float acc[4][4][4];
    #pragma unroll
    for (int i = 0; i < 4; i++)
        #pragma unroll
        for (int j = 0; j < 4; j++)
            #pragma unroll
            for (int q = 0; q < 4; q++) acc[i][j][q] = 0.f;

    const __half* Ab = A + (size_t)row0 * K;
    const __half* Bb = Bt + (size_t)col0 * K;
    int r0 = tid >> 2, c0 = tid & 3;
    int r1 = (tid + 256) >> 2, c1 = (tid + 256) & 3;

    // per-lane ldmatrix base offsets (bytes within a stage)
    int lrow = lane & 7, lq = lane >> 3;
    uint32_t aoff[4], boff[2];
    #pragma unroll
    for (int i = 0; i < 4; i++)
        aoff[i] = (uint32_t)(wr + i * 16 + lrow + (lq & 1) * 8) * 80 + (lq >> 1) * 16;
    #pragma unroll
    for (int jp = 0; jp < 2; jp++)
        boff[jp] = 10240u + (uint32_t)(wc + jp * 16 + lrow + (lq >> 1) * 8) * 80
                 + (lq & 1) * 16;

    uint32_t smb = sptr(hsm);

    #define LOAD_STAGE(st, k0)                                                 \
        do {                                                                   \
            uint32_t as = smb + (st) * STGB;                                   \
            uint32_t bs = as + 10240;                                          \
            CP_ASYNC16(as + r0 * 80 + c0 * 16, Ab + (size_t)r0 * K + (k0) + c0 * 8); \
            CP_ASYNC16(as + r1 * 80 + c1 * 16, Ab + (size_t)r1 * K + (k0) + c1 * 8); \
            CP_ASYNC16(bs + r0 * 80 + c0 * 16, Bb + (size_t)r0 * K + (k0) + c0 * 8); \
            CP_ASYNC16(bs + r1 * 80 + c1 * 16, Bb + (size_t)r1 * K + (k0) + c1 * 8); \
        } while (0)

    int ntiles = K >> 5;
    LOAD_STAGE(0, 0);  CP_COMMIT();
    if (ntiles > 1) LOAD_STAGE(1, 32);
    CP_COMMIT();

    int st = 0;
    for (int it = 0; it < ntiles; it++) {
        CP_WAIT1();
        __syncthreads();
        int nx = it + 2;
        int stn = st + 2; if (stn >= 3) stn -= 3;
        if (nx < ntiles) LOAD_STAGE(stn, nx << 5);
        CP_COMMIT();

        uint32_t sb = smb + st * STGB;
        #pragma unroll
        for (int ks = 0; ks < 2; ks++) {
            uint32_t ko = (uint32_t)(ks << 5);           // 16 halves = 32 bytes
            uint32_t af[4][4], bf[4][2];
            #pragma unroll
            for (int i = 0; i < 4; i++)
                LDSM4(af[i][0], af[i][1], af[i][2], af[i][3], sb + aoff[i] + ko);
            #pragma unroll
            for (int jp = 0; jp < 2; jp++)
                LDSM4(bf[2 * jp][0], bf[2 * jp][1], bf[2 * jp + 1][0],
                      bf[2 * jp + 1][1], sb + boff[jp] + ko);
            #pragma unroll
            for (int i = 0; i < 4; i++)
                #pragma unroll
                for (int j = 0; j < 4; j++)
                    mma16(acc[i][j], af[i], bf[j]);
        }
        if (++st == 3) st = 0;
    }
    #undef LOAD_STAGE

    #pragma unroll
    for (int i = 0; i < 4; i++)
        #pragma unroll
        for (int j = 0; j < 4; j++) {
            int cc0 = col0 + wc + j * 8 + tig * 2;
            #pragma unroll
            for (int h2 = 0; h2 < 2; h2++) {
                int r = row0 + wr + i * 16 + gid + h2 * 8;
                float v0 = acc[i][j][h2 * 2 + 0];
                float v1 = acc[i][j][h2 * 2 + 1];
                if (cc0 < Nreal) {
                    if (bias) v0 += bias[cc0];
                    if (res)  v0 += res[(size_t)r * Nreal + cc0];
                    if (relu) v0 = fmaxf(v0, 0.f);
                    acc[i][j][h2 * 2 + 0] = v0;
                    if (CoutH) CoutH[(size_t)r * Nreal + cc0] = __float2half_rn(v0);
                    else       Cout [(size_t)r * Nreal + cc0] = rnd ? tf32r(v0) : v0;
                }
                if (cc0 + 1 < Nreal) {
                    if (bias) v1 += bias[cc0 + 1];
                    if (res)  v1 += res[(size_t)r * Nreal + cc0 + 1];
                    if (relu) v1 = fmaxf(v1, 0.f);
                    acc[i][j][h2 * 2 + 1] = v1;
                    if (CoutH) CoutH[(size_t)r * Nreal + cc0 + 1] = __float2half_rn(v1);
                    else       Cout [(size_t)r * Nreal + cc0 + 1] = rnd ? tf32r(v1) : v1;
                }
            }
        }

    // fused partial logsumexp over this CTA's 128 columns (LM head only)
    if (lsem) {
        float2* sls = (float2*)hsm;
        __syncthreads();
        #pragma unroll
        for (int i = 0; i < 4; i++)
            #pragma unroll
            for (int h2 = 0; h2 < 2; h2++) {
                float m = -1e30f;
                #pragma unroll
                for (int j = 0; j < 4; j++) {
                    int c = col0 + wc + j * 8 + tig * 2;
                    if (c     < Nreal) m = fmaxf(m, acc[i][j][h2 * 2 + 0]);
                    if (c + 1 < Nreal) m = fmaxf(m, acc[i][j][h2 * 2 + 1]);
                }
                float s = 0.f;
                #pragma unroll
                for (int j = 0; j < 4; j++) {
                    int c = col0 + wc + j * 8 + tig * 2;
                    if (c     < Nreal) s += __expf(acc[i][j][h2 * 2 + 0] - m);
                    if (c + 1 < Nreal) s += __expf(acc[i][j][h2 * 2 + 1] - m);
                }
                #pragma unroll
                for (int o = 1; o <= 2; o <<= 1) {
                    float mo = __shfl_xor_sync(0xffffffffu, m, o);
                    float so = __shfl_xor_sync(0xffffffffu, s, o);
                    float M = fmaxf(m, mo);
                    s = s * __expf(m - M) + so * __expf(mo - M);
                    m = M;
                }
                if (tig == 0) {
                    int rr = wr + i * 16 + gid + h2 * 8;
                    sls[rr * 4 + (wid & 3)] = make_float2(m, s);
                }
            }
        __syncthreads();
        if (tid < 128) {
            float m = -1e30f, s = 0.f;
            #pragma unroll
            for (int g = 0; g < 4; g++) {
                float2 p = sls[tid * 4 + g];
                float M = fmaxf(m, p.x);
                s = s * __expf(m - M) + p.y * __expf(p.x - M);
                m = M;
            }
            size_t idx = (size_t)(row0 + tid) * gx + blockIdx.x;
            lsem[idx] = m;
            lses[idx] = s;
        }
    }
}

// ---------------- loss reduce --------------------------------------------------
__global__ void zero_loss_kernel() { g_loss = 0.f; }

__global__ void loss_reduce_kernel(const float* __restrict__ logits,
                                   const int* __restrict__ target, int gx) {
    int row = blockIdx.x, tid = threadIdx.x;   // 128 threads
    float m = -1e30f, s = 0.f;
    for (int i = tid; i < gx; i += 128) {
        size_t idx = (size_t)row * gx + i;
        float pm = g_lsem[idx], ps = g_lses[idx];
        float M = fmaxf(m, pm);
        s = s * __expf(m - M) + ps * __expf(pm - M);
        m = M;
    }
    #pragma unroll
    for (int o = 16; o; o >>= 1) {
        float mo = __shfl_xor_sync(0xffffffffu, m, o);
        float so = __shfl_xor_sync(0xffffffffu, s, o);
        float M = fmaxf(m, mo);
        s = s * __expf(m - M) + so * __expf(mo - M);
        m = M;
    }
    __shared__ float rm[4], rs[4];
    if ((tid & 31) == 0) { rm[tid >> 5] = m; rs[tid >> 5] = s; }
    __syncthreads();
    if (tid == 0) {
        float M = fmaxf(fmaxf(rm[0], rm[1]), fmaxf(rm[2], rm[3]));
        float S = 0.f;
        #pragma unroll
        for (int i = 0; i < 4; i++) S += rs[i] * __expf(rm[i] - M);
        float lse = M + logf(S);
        atomicAdd(&g_loss, lse - logits[(size_t)row * VV + target[row]]);
    }
}

__global__ void finalize_loss_kernel(float* __restrict__ out) {
    out[(size_t)BT * VV] = g_loss * (1.0f / BT);
}

// ---------------- fused flash attention ---------------------------------------
#define FBQ 128
#define FBS 64
#define KLD 68
#define VLD 72
#define PLD 136
#define FSMEM ((FBS*KLD + FBS*VLD + FBS*PLD) * 4)

__global__ __launch_bounds__(256, 1)
void flash_kernel(const float* __restrict__ qkv, __half* __restrict__ outp) {
    extern __shared__ float fsm[];
    float* Ks = fsm;
    float* Vs = fsm + FBS * KLD;
    float* Ps = fsm + FBS * (KLD + VLD);

    int tid = threadIdx.x;
    int lane = tid & 31, gid = lane >> 2, tig = lane & 3;
    int wid = tid >> 5;
    int wrow = wid * 16;
    int q0 = (gridDim.x - 1 - blockIdx.x) * FBQ;
    int z = blockIdx.y;
    int b = z >> 3, h = z & 7;
    const float* qbase = qkv + (size_t)b * TT * (3 * CC) + h * HDIM;
    const float* kbase = qbase + CC;
    const float* vbase = qbase + 2 * CC;

    uint32_t aQ[8][4];
    {
        int t0 = q0 + wrow + gid;
        const float* q0p = qbase + (size_t)t0 * (3 * CC);
        const float* q1p = q0p + 8 * (3 * CC);
        #pragma unroll
        for (int ks = 0; ks < 8; ks++) {
            aQ[ks][0] = __float_as_uint(q0p[ks * 8 + tig]);
            aQ[ks][1] = __float_as_uint(q1p[ks * 8 + tig]);
            aQ[ks][2] = __float_as_uint(q0p[ks * 8 + tig + 4]);
            aQ[ks][3] = __float_as_uint(q1p[ks * 8 + tig + 4]);
        }
    }
    float oAcc[8][4];
    #pragma unroll
    for (int j = 0; j < 8; j++)
        #pragma unroll
        for (int q = 0; q < 4; q++) oAcc[j][q] = 0.f;
    float m0 = -1e30f, m1 = -1e30f, l0 = 0.f, l1 = 0.f;
    int t0g = q0 + wrow + gid, t1g = t0g + 8;
    int nTiles = q0 / FBS + 2;

    for (int it = 0; it < nTiles; it++) {
        int s0 = it * FBS;
        __syncthreads();
        #pragma unroll
        for (int i = 0; i < 4; i++) {
            int f4 = tid + i * 256;
            int r = f4 >> 4, kc = (f4 & 15) << 2;
            float4 kv = *reinterpret_cast<const float4*>(
                kbase + (size_t)(s0 + r) * (3 * CC) + kc);
            *reinterpret_cast<float4*>(Ks + r * KLD + kc) = kv;
            float4 vv = *reinterpret_cast<const float4*>(
                vbase + (size_t)(s0 + r) * (3 * CC) + kc);
            *reinterpret_cast<float4*>(Vs + r * VLD + kc) = vv;
        }
        __syncthreads();

        float sAcc[8][4];
        #pragma unroll
        for (int j = 0; j < 8; j++)
            #pragma unroll
            for (int q = 0; q < 4; q++) sAcc[j][q] = 0.f;
        #pragma unroll
        for (int ks = 0; ks < 8; ks++) {
            int kb = ks * 8;
            #pragma unroll
            for (int j = 0; j < 8; j++) {
                int n = j * 8 + gid;
                uint32_t bb[2];
                bb[0] = __float_as_uint(Ks[n * KLD + kb + tig]);
                bb[1] = __float_as_uint(Ks[n * KLD + kb + tig + 4]);
                mma8(sAcc[j], aQ[ks], bb);
            }
        }
        #pragma unroll
        for (int j = 0; j < 8; j++) {
            int sb = s0 + j * 8 + tig * 2;
            #pragma unroll
            for (int q = 0; q < 4; q++) {
                float v = sAcc[j][q] * 0.125f;
                int s_g = sb + (q & 1);
                int t_g = (q < 2) ? t0g : t1g;
                sAcc[j][q] = (s_g > t_g) ? -1e30f : v;
            }
        }
        float rm0 = -1e30f, rm1 = -1e30f;
        #pragma unroll
        for (int j = 0; j < 8; j++) {
            rm0 = fmaxf(rm0, fmaxf(sAcc[j][0], sAcc[j][1]));
            rm1 = fmaxf(rm1, fmaxf(sAcc[j][2], sAcc[j][3]));
        }
        #pragma unroll
        for (int o = 1; o <= 2; o <<= 1) {
            rm0 = fmaxf(rm0, __shfl_xor_sync(0xffffffffu, rm0, o));
            rm1 = fmaxf(rm1, __shfl_xor_sync(0xffffffffu, rm1, o));
        }
        float nm0 = fmaxf(m0, rm0), nm1 = fmaxf(m1, rm1);
        float a0 = __expf(m0 - nm0), a1 = __expf(m1 - nm1);
        float rs0 = 0.f, rs1 = 0.f;
        #pragma unroll
        for (int j = 0; j < 8; j++) {
            int sb = (j * 8 + tig * 2) * PLD;
            float p0 = __expf(sAcc[j][0] - nm0);
            float p1 = __expf(sAcc[j][1] - nm0);
            float p2 = __expf(sAcc[j][2] - nm1);
            float p3 = __expf(sAcc[j][3] - nm1);
            rs0 += p0 + p1; rs1 += p2 + p3;
            int tc0 = wrow + gid, tc1 = tc0 + 8;
            Ps[sb       + tc0] = tf32r(p0);
            Ps[sb + PLD + tc0] = tf32r(p1);
            Ps[sb       + tc1] = tf32r(p2);
            Ps[sb + PLD + tc1] = tf32r(p3);
        }
        #pragma unroll
        for (int o = 1; o <= 2; o <<= 1) {
            rs0 += __shfl_xor_sync(0xffffffffu, rs0, o);
            rs1 += __shfl_xor_sync(0xffffffffu, rs1, o);
        }
        l0 = l0 * a0 + rs0;
        l1 = l1 * a1 + rs1;
        m0 = nm0; m1 = nm1;
        #pragma unroll
        for (int j = 0; j < 8; j++) {
            oAcc[j][0] *= a0; oAcc[j][1] *= a0;
            oAcc[j][2] *= a1; oAcc[j][3] *= a1;
        }
        __syncwarp();
        #pragma unroll
        for (int ks = 0; ks < 8; ks++) {
            int kb = ks * 8;
            uint32_t aP[4];
            int mr = wrow + gid;
            aP[0] = __float_as_uint(Ps[(kb + tig    ) * PLD + mr    ]);
            aP[1] = __float_as_uint(Ps[(kb + tig    ) * PLD + mr + 8]);
            aP[2] = __float_as_uint(Ps[(kb + tig + 4) * PLD + mr    ]);
            aP[3] = __float_as_uint(Ps[(kb + tig + 4) * PLD + mr + 8]);
            #pragma unroll
            for (int j = 0; j < 8; j++) {
                int n = j * 8 + gid;
                uint32_t bb[2];
                bb[0] = __float_as_uint(Vs[(kb + tig    ) * VLD + n]);
                bb[1] = __float_as_uint(Vs[(kb + tig + 4) * VLD + n]);
                mma8(oAcc[j], aP, bb);
            }
        }
    }
    float inv0 = 1.f / l0, inv1 = 1.f / l1;
    __half* o0 = outp + (size_t)(b * TT + t0g) * CC + h * HDIM;
    __half* o1 = outp + (size_t)(b * TT + t1g) * CC + h * HDIM;
    #pragma unroll
    for (int j = 0; j < 8; j++) {
        int d = j * 8 + tig * 2;
        o0[d]     = __float2half_rn(oAcc[j][0] * inv0);
        o0[d + 1] = __float2half_rn(oAcc[j][1] * inv0);
        o1[d]     = __float2half_rn(oAcc[j][2] * inv1);
        o1[d + 1] = __float2half_rn(oAcc[j][3] * inv1);
    }
}

// ---------------- launch ------------------------------------------------------
extern "C" void kernel_launch(void* const* d_in, const int* in_sizes, int n_in,
                              void* d_out, int out_size) {
    const int*   x      = (const int*)  d_in[0];
    const int*   target = (const int*)  d_in[1];
    const float* tok    = (const float*)d_in[2];
    const float* pos    = (const float*)d_in[3];
    const float* ln1s   = (const float*)d_in[4];
    const float* ln1b   = (const float*)d_in[5];
    const float* wq     = (const float*)d_in[6];
    const float* wk     = (const float*)d_in[7];
    const float* wv     = (const float*)d_in[8];
    const float* wproj  = (const float*)d_in[9];
    const float* bproj  = (const float*)d_in[10];
    const float* ln2s   = (const float*)d_in[11];
    const float* ln2b   = (const float*)d_in[12];
    const float* wff1   = (const float*)d_in[13];
    const float* bff1   = (const float*)d_in[14];
    const float* wff2   = (const float*)d_in[15];
    const float* bff2   = (const float*)d_in[16];
    const float* lnfs   = (const float*)d_in[17];
    const float* lnfb   = (const float*)d_in[18];
    const float* lmw    = (const float*)d_in[19];
    const float* lmb    = (const float*)d_in[20];
    float* out = (float*)d_out;

    float  *p_h, *p_qkv, *p_lsem, *p_lses;
    __half *p_ainh, *p_attnh, *p_ffh, *p_wqkvT, *p_wpT, *p_w1T, *p_w2T, *p_lmwT;
    cudaGetSymbolAddress((void**)&p_h,     g_h);
    cudaGetSymbolAddress((void**)&p_qkv,   g_qkv);
    cudaGetSymbolAddress((void**)&p_lsem,  g_lsem);
    cudaGetSymbolAddress((void**)&p_lses,  g_lses);
    cudaGetSymbolAddress((void**)&p_ainh,  g_ainh);
    cudaGetSymbolAddress((void**)&p_attnh, g_attnh);
    cudaGetSymbolAddress((void**)&p_ffh,   g_ffh);
    cudaGetSymbolAddress((void**)&p_wqkvT, g_wqkvT);
    cudaGetSymbolAddress((void**)&p_wpT,   g_wpT);
    cudaGetSymbolAddress((void**)&p_w1T,   g_w1T);
    cudaGetSymbolAddress((void**)&p_w2T,   g_w2T);
    cudaGetSymbolAddress((void**)&p_lmwT,  g_lmwT);

    static int attr_done = 0;
    if (!attr_done) {
        cudaFuncSetAttribute(flash_kernel,
                             cudaFuncAttributeMaxDynamicSharedMemorySize, FSMEM);
        cudaFuncSetAttribute(gemm_fp16_kernel,
                             cudaFuncAttributeMaxDynamicSharedMemorySize, HSMEM);
        attr_done = 1;
    }

    prep_kernel<<<T_ALL, dim3(32, 8)>>>(wq, wk, wv, wproj, wff1, wff2, lmw);
    embed_kernel<<<(BT * CC + 255) / 256, 256>>>(x, tok, pos);

    dim3 gQKV(12, 32), gC2(4, 32), gFF(16, 32), gV(GXV, 32);
    dim3 gFA(TT / FBQ, BHZ);

    for (int l = 0; l < LLAY; l++) {
        ln_kernel<<<BT, 256>>>(p_h, ln1s + l * CC, ln1b + l * CC, p_ainh);
        gemm_fp16_kernel<<<gQKV, 256, HSMEM>>>(
            p_ainh, p_wqkvT + (size_t)l * 3 * CC * CC, p_qkv, nullptr,
            3 * CC, CC, nullptr, nullptr, 0, 1, nullptr, nullptr, 0);
        flash_kernel<<<gFA, 256, FSMEM>>>(p_qkv, p_attnh);
        gemm_fp16_kernel<<<gC2, 256, HSMEM>>>(
            p_attnh, p_wpT + (size_t)l * CC * CC, p_h, nullptr,
            CC, CC, bproj + l * CC, p_h, 0, 0, nullptr, nullptr, 0);
        ln_kernel<<<BT, 256>>>(p_h, ln2s + l * CC, ln2b + l * CC, p_ainh);
        gemm_fp16_kernel<<<gFF, 256, HSMEM>>>(
            p_ainh, p_w1T + (size_t)l * FFD * CC, nullptr, p_ffh,
            FFD, CC, bff1 + l * FFD, nullptr, 1, 0, nullptr, nullptr, 0);
        gemm_fp16_kernel<<<gC2, 256, HSMEM>>>(
            p_ffh, p_w2T + (size_t)l * CC * FFD, p_h, nullptr,
            CC, FFD, bff2 + l * CC, p_h, 0, 0, nullptr, nullptr, 0);
    }

    ln_kernel<<<BT, 256>>>(p_h, lnfs, lnfb, p_ainh);
    gemm_fp16_kernel<<<gV, 256, HSMEM>>>(
        p_ainh, p_lmwT, out, nullptr, VV, CC, lmb, nullptr, 0, 0,
        p_lsem, p_lses, GXV);

    if ((long long)out_size > (long long)BT * VV) {
        zero_loss_kernel<<<1, 1>>>();
        loss_reduce_kernel<<<BT, 128>>>(out, target, GXV);
        finalize_loss_kernel<<<1, 1>>>(out);
    }
}

// round 15
// speedup vs baseline: 1.6836x; 1.0007x over previous
#include <cuda_runtime.h>
#include <cuda_fp16.h>
#include <math.h>
#include <stdint.h>

#define BATCH 2
#define TT    2048
#define BT    4096
#define CC    512
#define HH    8
#define HDIM  64
#define LLAY  4
#define VV    50257
#define VPAD  50304               // multiple of 128
#define FFD   2048
#define LNEPS 1e-5f
#define BHZ   16
#define GXV   (VPAD/128)          // 393 LM-head col tiles

// ---------------- scratch -----------------------------------------------------
__device__ float  g_h    [BT*CC];
__device__ __half g_ainh [BT*CC];
__device__ float  g_qkv  [BT*3*CC];
__device__ __half g_attnh[BT*CC];
__device__ __half g_ffh  [(size_t)BT*FFD];
__device__ __half g_wqkvT[(size_t)LLAY*3*CC*CC];
__device__ __half g_wpT  [(size_t)LLAY*CC*CC];
__device__ __half g_w1T  [(size_t)LLAY*FFD*CC];
__device__ __half g_w2T  [(size_t)LLAY*CC*FFD];
__device__ __half g_lmwT [(size_t)VPAD*CC];
__device__ float  g_lsem [(size_t)BT*400];
__device__ float  g_lses [(size_t)BT*400];
__device__ float  g_loss;

// ---------------- helpers ------------------------------------------------------
__device__ __forceinline__ float warpSum(float v) {
    #pragma unroll
    for (int o = 16; o; o >>= 1) v += __shfl_xor_sync(0xffffffffu, v, o);
    return v;
}
__device__ __forceinline__ float tf32r(float x) {
    uint32_t u;
    asm("cvt.rna.tf32.f32 %0, %1;" : "=r"(u) : "f"(x));
    return __uint_as_float(u);
}
__device__ __forceinline__ void mma8(float* c, const uint32_t* a, const uint32_t* b) {
    asm volatile(
        "mma.sync.aligned.m16n8k8.row.col.f32.tf32.tf32.f32 "
        "{%0,%1,%2,%3}, {%4,%5,%6,%7}, {%8,%9}, {%0,%1,%2,%3};"
        : "+f"(c[0]), "+f"(c[1]), "+f"(c[2]), "+f"(c[3])
        : "r"(a[0]), "r"(a[1]), "r"(a[2]), "r"(a[3]), "r"(b[0]), "r"(b[1]));
}
__device__ __forceinline__ void mma16(float* c, const uint32_t* a, const uint32_t* b) {
    asm volatile(
        "mma.sync.aligned.m16n8k16.row.col.f32.f16.f16.f32 "
        "{%0,%1,%2,%3}, {%4,%5,%6,%7}, {%8,%9}, {%0,%1,%2,%3};"
        : "+f"(c[0]), "+f"(c[1]), "+f"(c[2]), "+f"(c[3])
        : "r"(a[0]), "r"(a[1]), "r"(a[2]), "r"(a[3]), "r"(b[0]), "r"(b[1]));
}
#define LDSM4(r0, r1, r2, r3, addr) \
    asm volatile("ldmatrix.sync.aligned.m8n8.x4.shared.b16 {%0,%1,%2,%3}, [%4];" \
        : "=r"(r0), "=r"(r1), "=r"(r2), "=r"(r3) : "r"(addr))
__device__ __forceinline__ uint32_t sptr(const void* p) {
    return (uint32_t)__cvta_generic_to_shared(p);
}
#define CP_ASYNC16(d, s) \
    asm volatile("cp.async.ca.shared.global [%0], [%1], 16;\n" :: "r"(d), "l"(s))
#define CP_COMMIT() asm volatile("cp.async.commit_group;\n" ::: "memory")
#define CP_WAIT1()  asm volatile("cp.async.wait_group 1;\n"  ::: "memory")

// ---------------- fused weight prep (single launch) ---------------------------
#define T_QKV (48*16*LLAY)
#define T_WP  (16*16*LLAY)
#define T_W1  (64*16*LLAY)
#define T_W2  (16*64*LLAY)
#define T_LMW ((VPAD/32)*16)
#define T_ALL (T_QKV+T_WP+T_W1+T_W2+T_LMW)

__device__ __forceinline__ void trans_tile(__half* dst, const float* src,
                                           int R, int Creal, int xt, int yt,
                                           float (*t)[33], int tx, int ty) {
    int c0 = xt * 32, r0 = yt * 32;
    #pragma unroll
    for (int i = 0; i < 32; i += 8) {
        int c = c0 + tx;
        t[tx][ty + i] = (c < Creal) ? src[(size_t)(r0 + ty + i) * Creal + c] : 0.f;
    }
    __syncthreads();
    #pragma unroll
    for (int i = 0; i < 32; i += 8)
        dst[(size_t)(c0 + ty + i) * R + r0 + tx] = __float2half_rn(t[ty + i][tx]);
}

__global__ void prep_kernel(const float* __restrict__ wq, const float* __restrict__ wk,
                            const float* __restrict__ wv, const float* __restrict__ wproj,
                            const float* __restrict__ wff1, const float* __restrict__ wff2,
                            const float* __restrict__ lmw) {
    __shared__ float t[32][33];
    int tx = threadIdx.x, ty = threadIdx.y;
    int bid = blockIdx.x;
    if (bid < T_QKV) {
        int l = bid / (48 * 16), rem = bid % (48 * 16);
        int xt = rem % 48, yt = rem / 48;
        int j0 = xt * 32, c0 = yt * 32;
        int which = j0 >> 9, h = (j0 & 511) >> 6, d0 = j0 & 63;
        const float* w = (which == 0) ? wq : (which == 1) ? wk : wv;
        const float* s = w + (((size_t)l * HH + h) * CC) * HDIM;
        #pragma unroll
        for (int i = 0; i < 32; i += 8)
            t[tx][ty + i] = s[(size_t)(c0 + ty + i) * HDIM + d0 + tx];
        __syncthreads();
        __half* d = g_wqkvT + ((size_t)l * (3 * CC) + j0) * CC + c0;
        #pragma unroll
        for (int i = 0; i < 32; i += 8)
            d[(size_t)(ty + i) * CC + tx] = __float2half_rn(t[ty + i][tx]);
        return;
    }
    bid -= T_QKV;
    if (bid < T_WP) {
        int l = bid / 256, rem = bid % 256;
        trans_tile(g_wpT + (size_t)l * CC * CC, wproj + (size_t)l * CC * CC,
                   CC, CC, rem % 16, rem / 16, t, tx, ty);
        return;
    }
    bid -= T_WP;
    if (bid < T_W1) {
        int l = bid / 1024, rem = bid % 1024;
        trans_tile(g_w1T + (size_t)l * FFD * CC, wff1 + (size_t)l * CC * FFD,
                   CC, FFD, rem % 64, rem / 64, t, tx, ty);
        return;
    }
    bid -= T_W1;
    if (bid < T_W2) {
        int l = bid / 1024, rem = bid % 1024;
        trans_tile(g_w2T + (size_t)l * CC * FFD, wff2 + (size_t)l * FFD * CC,
                   FFD, CC, rem % 16, rem / 16, t, tx, ty);
        return;
    }
    bid -= T_W2;
    trans_tile(g_lmwT, lmw, CC, VV, bid % (VPAD / 32), bid / (VPAD / 32), t, tx, ty);
}

// ---------------- embedding / layernorm ---------------------------------------
__global__ void embed_kernel(const int* __restrict__ x, const float* __restrict__ tok,
                             const float* __restrict__ pos) {
    int i = blockIdx.x * blockDim.x + threadIdx.x;
    if (i >= BT * CC) return;
    int c = i % CC, bt = i / CC, t = bt % TT;
    g_h[i] = tok[(size_t)x[bt] * CC + c] + pos[(size_t)t * CC + c];
}

__global__ void ln_kernel(const float* __restrict__ in, const float* __restrict__ sc,
                          const float* __restrict__ bi, __half* __restrict__ out) {
    int row = blockIdx.x, tid = threadIdx.x;
    const float* r = in + (size_t)row * CC;
    float a = r[tid], b = r[tid + 256];
    float s = a + b, q = a * a + b * b;
    s = warpSum(s); q = warpSum(q);
    __shared__ float rs[8], rq[8];
    if ((tid & 31) == 0) { rs[tid >> 5] = s; rq[tid >> 5] = q; }
    __syncthreads();
    __shared__ float s_mean, s_rstd;
    if (tid == 0) {
        float S = 0.f, Q = 0.f;
        #pragma unroll
        for (int i = 0; i < 8; i++) { S += rs[i]; Q += rq[i]; }
        float m = S * (1.0f / CC);
        s_mean = m; s_rstd = rsqrtf(Q * (1.0f / CC) - m * m + LNEPS);
    }
    __syncthreads();
    float m = s_mean, rstd = s_rstd;
    __half* o = out + (size_t)row * CC;
    o[tid]       = __float2half_rn((a - m) * rstd * sc[tid]       + bi[tid]);
    o[tid + 256] = __float2half_rn((b - m) * rstd * sc[tid + 256] + bi[tid + 256]);
}

// ---------------- fp16 GEMM: C[M,N] = A[M,K] @ Bt[N,K]^T ----------------------
// 128x128 tile, BK=32 halves, 256 thr (8 warps 2x4, 64x32 each), 3-stage.
// ldmatrix.x4 fragment loads: 6 LDSM + 32 HMMA per k16-slice pair.
#define ALD 40
#define STGB 20480
#define HSMEM (3*STGB)

__global__ __launch_bounds__(256, 2)
void gemm_fp16_kernel(const __half* __restrict__ A, const __half* __restrict__ Bt,
                      float* __restrict__ Cout, __half* __restrict__ CoutH,
                      int Nreal, int K,
                      const float* __restrict__ bias, const float* __restrict__ res,
                      int relu, int rnd,
                      float* __restrict__ lsem, float* __restrict__ lses, int gx) {
    extern __shared__ __align__(16) char hsm[];
    int tid = threadIdx.x;
    int row0 = blockIdx.y << 7, col0 = blockIdx.x << 7;
    int lane = tid & 31, gid = lane >> 2, tig = lane & 3;
    int wid = tid >> 5;
    int wr = (wid >> 2) * 64;
    int wc = (wid & 3) * 32;

    float acc[4][4][4];
    #pragma unroll
    for (int i = 0; i < 4; i++)
        #pragma unroll
        for (int j = 0; j < 4; j++)
            #pragma unroll
            for (int q = 0; q < 4; q++) acc[i][j][q] = 0.f;

    const __half* Ab = A + (size_t)row0 * K;
    const __half* Bb = Bt + (size_t)col0 * K;
    int r0 = tid >> 2, c0 = tid & 3;
    int r1 = (tid + 256) >> 2, c1 = (tid + 256) & 3;

    // per-lane ldmatrix base offsets (bytes within a stage)
    int lrow = lane & 7, lq = lane >> 3;
    uint32_t aoff[4], boff[2];
    #pragma unroll
    for (int i = 0; i < 4; i++)
        aoff[i] = (uint32_t)(wr + i * 16 + lrow + (lq & 1) * 8) * 80 + (lq >> 1) * 16;
    #pragma unroll
    for (int jp = 0; jp < 2; jp++)
        boff[jp] = 10240u + (uint32_t)(wc + jp * 16 + lrow + (lq >> 1) * 8) * 80
                 + (lq & 1) * 16;

    uint32_t smb = sptr(hsm);

    #define LOAD_STAGE(st, k0)                                                 \
        do {                                                                   \
            uint32_t as = smb + (st) * STGB;                                   \
            uint32_t bs = as + 10240;                                          \
            CP_ASYNC16(as + r0 * 80 + c0 * 16, Ab + (size_t)r0 * K + (k0) + c0 * 8); \
            CP_ASYNC16(as + r1 * 80 + c1 * 16, Ab + (size_t)r1 * K + (k0) + c1 * 8); \
            CP_ASYNC16(bs + r0 * 80 + c0 * 16, Bb + (size_t)r0 * K + (k0) + c0 * 8); \
            CP_ASYNC16(bs + r1 * 80 + c1 * 16, Bb + (size_t)r1 * K + (k0) + c1 * 8); \
        } while (0)

    int ntiles = K >> 5;
    LOAD_STAGE(0, 0);  CP_COMMIT();
    if (ntiles > 1) LOAD_STAGE(1, 32);
    CP_COMMIT();

    int st = 0;
    for (int it = 0; it < ntiles; it++) {
        CP_WAIT1();
        __syncthreads();
        int nx = it + 2;
        int stn = st + 2; if (stn >= 3) stn -= 3;
        if (nx < ntiles) LOAD_STAGE(stn, nx << 5);
        CP_COMMIT();

        uint32_t sb = smb + st * STGB;
        #pragma unroll
        for (int ks = 0; ks < 2; ks++) {
            uint32_t ko = (uint32_t)(ks << 5);           // 16 halves = 32 bytes
            uint32_t af[4][4], bf[4][2];
            #pragma unroll
            for (int i = 0; i < 4; i++)
                LDSM4(af[i][0], af[i][1], af[i][2], af[i][3], sb + aoff[i] + ko);
            #pragma unroll
            for (int jp = 0; jp < 2; jp++)
                LDSM4(bf[2 * jp][0], bf[2 * jp][1], bf[2 * jp + 1][0],
                      bf[2 * jp + 1][1], sb + boff[jp] + ko);
            #pragma unroll
            for (int i = 0; i < 4; i++)
                #pragma unroll
                for (int j = 0; j < 4; j++)
                    mma16(acc[i][j], af[i], bf[j]);
        }
        if (++st == 3) st = 0;
    }
    #undef LOAD_STAGE

    #pragma unroll
    for (int i = 0; i < 4; i++)
        #pragma unroll
        for (int j = 0; j < 4; j++) {
            int cc0 = col0 + wc + j * 8 + tig * 2;
            #pragma unroll
            for (int h2 = 0; h2 < 2; h2++) {
                int r = row0 + wr + i * 16 + gid + h2 * 8;
                float v0 = acc[i][j][h2 * 2 + 0];
                float v1 = acc[i][j][h2 * 2 + 1];
                if (cc0 < Nreal) {
                    if (bias) v0 += bias[cc0];
                    if (res)  v0 += res[(size_t)r * Nreal + cc0];
                    if (relu) v0 = fmaxf(v0, 0.f);
                    acc[i][j][h2 * 2 + 0] = v0;
                    if (CoutH) CoutH[(size_t)r * Nreal + cc0] = __float2half_rn(v0);
                    else       Cout [(size_t)r * Nreal + cc0] = rnd ? tf32r(v0) : v0;
                }
                if (cc0 + 1 < Nreal) {
                    if (bias) v1 += bias[cc0 + 1];
                    if (res)  v1 += res[(size_t)r * Nreal + cc0 + 1];
                    if (relu) v1 = fmaxf(v1, 0.f);
                    acc[i][j][h2 * 2 + 1] = v1;
                    if (CoutH) CoutH[(size_t)r * Nreal + cc0 + 1] = __float2half_rn(v1);
                    else       Cout [(size_t)r * Nreal + cc0 + 1] = rnd ? tf32r(v1) : v1;
                }
            }
        }

    // fused partial logsumexp over this CTA's 128 columns (LM head only)
    if (lsem) {
        float2* sls = (float2*)hsm;
        __syncthreads();
        #pragma unroll
        for (int i = 0; i < 4; i++)
            #pragma unroll
            for (int h2 = 0; h2 < 2; h2++) {
                float m = -1e30f;
                #pragma unroll
                for (int j = 0; j < 4; j++) {
                    int c = col0 + wc + j * 8 + tig * 2;
                    if (c     < Nreal) m = fmaxf(m, acc[i][j][h2 * 2 + 0]);
                    if (c + 1 < Nreal) m = fmaxf(m, acc[i][j][h2 * 2 + 1]);
                }
                float s = 0.f;
                #pragma unroll
                for (int j = 0; j < 4; j++) {
                    int c = col0 + wc + j * 8 + tig * 2;
                    if (c     < Nreal) s += __expf(acc[i][j][h2 * 2 + 0] - m);
                    if (c + 1 < Nreal) s += __expf(acc[i][j][h2 * 2 + 1] - m);
                }
                #pragma unroll
                for (int o = 1; o <= 2; o <<= 1) {
                    float mo = __shfl_xor_sync(0xffffffffu, m, o);
                    float so = __shfl_xor_sync(0xffffffffu, s, o);
                    float M = fmaxf(m, mo);
                    s = s * __expf(m - M) + so * __expf(mo - M);
                    m = M;
                }
                if (tig == 0) {
                    int rr = wr + i * 16 + gid + h2 * 8;
                    sls[rr * 4 + (wid & 3)] = make_float2(m, s);
                }
            }
        __syncthreads();
        if (tid < 128) {
            float m = -1e30f, s = 0.f;
            #pragma unroll
            for (int g = 0; g < 4; g++) {
                float2 p = sls[tid * 4 + g];
                float M = fmaxf(m, p.x);
                s = s * __expf(m - M) + p.y * __expf(p.x - M);
                m = M;
            }
            size_t idx = (size_t)(row0 + tid) * gx + blockIdx.x;
            lsem[idx] = m;
            lses[idx] = s;
        }
    }
}

// ---------------- loss reduce --------------------------------------------------
__global__ void zero_loss_kernel() { g_loss = 0.f; }

__global__ void loss_reduce_kernel(const float* __restrict__ logits,
                                   const int* __restrict__ target, int gx) {
    int row = blockIdx.x, tid = threadIdx.x;   // 128 threads
    float m = -1e30f, s = 0.f;
    for (int i = tid; i < gx; i += 128) {
        size_t idx = (size_t)row * gx + i;
        float pm = g_lsem[idx], ps = g_lses[idx];
        float M = fmaxf(m, pm);
        s = s * __expf(m - M) + ps * __expf(pm - M);
        m = M;
    }
    #pragma unroll
    for (int o = 16; o; o >>= 1) {
        float mo = __shfl_xor_sync(0xffffffffu, m, o);
        float so = __shfl_xor_sync(0xffffffffu, s, o);
        float M = fmaxf(m, mo);
        s = s * __expf(m - M) + so * __expf(mo - M);
        m = M;
    }
    __shared__ float rm[4], rs[4];
    if ((tid & 31) == 0) { rm[tid >> 5] = m; rs[tid >> 5] = s; }
    __syncthreads();
    if (tid == 0) {
        float M = fmaxf(fmaxf(rm[0], rm[1]), fmaxf(rm[2], rm[3]));
        float S = 0.f;
        #pragma unroll
        for (int i = 0; i < 4; i++) S += rs[i] * __expf(rm[i] - M);
        float lse = M + logf(S);
        atomicAdd(&g_loss, lse - logits[(size_t)row * VV + target[row]]);
    }
}

__global__ void finalize_loss_kernel(float* __restrict__ out) {
    out[(size_t)BT * VV] = g_loss * (1.0f / BT);
}

// ---------------- fused flash attention ---------------------------------------
#define FBQ 128
#define FBS 64
#define KLD 68
#define VLD 72
#define PLD 136
#define FSMEM ((FBS*KLD + FBS*VLD + FBS*PLD) * 4)

__global__ __launch_bounds__(256, 1)
void flash_kernel(const float* __restrict__ qkv, __half* __restrict__ outp) {
    extern __shared__ float fsm[];
    float* Ks = fsm;
    float* Vs = fsm + FBS * KLD;
    float* Ps = fsm + FBS * (KLD + VLD);

    int tid = threadIdx.x;
    int lane = tid & 31, gid = lane >> 2, tig = lane & 3;
    int wid = tid >> 5;
    int wrow = wid * 16;
    int q0 = (gridDim.x - 1 - blockIdx.x) * FBQ;
    int z = blockIdx.y;
    int b = z >> 3, h = z & 7;
    const float* qbase = qkv + (size_t)b * TT * (3 * CC) + h * HDIM;
    const float* kbase = qbase + CC;
    const float* vbase = qbase + 2 * CC;

    uint32_t aQ[8][4];
    {
        int t0 = q0 + wrow + gid;
        const float* q0p = qbase + (size_t)t0 * (3 * CC);
        const float* q1p = q0p + 8 * (3 * CC);
        #pragma unroll
        for (int ks = 0; ks < 8; ks++) {
            aQ[ks][0] = __float_as_uint(q0p[ks * 8 + tig]);
            aQ[ks][1] = __float_as_uint(q1p[ks * 8 + tig]);
            aQ[ks][2] = __float_as_uint(q0p[ks * 8 + tig + 4]);
            aQ[ks][3] = __float_as_uint(q1p[ks * 8 + tig + 4]);
        }
    }
    float oAcc[8][4];
    #pragma unroll
    for (int j = 0; j < 8; j++)
        #pragma unroll
        for (int q = 0; q < 4; q++) oAcc[j][q] = 0.f;
    float m0 = -1e30f, m1 = -1e30f, l0 = 0.f, l1 = 0.f;
    int t0g = q0 + wrow + gid, t1g = t0g + 8;
    int nTiles = q0 / FBS + 2;

    for (int it = 0; it < nTiles; it++) {
        int s0 = it * FBS;
        __syncthreads();
        #pragma unroll
        for (int i = 0; i < 4; i++) {
            int f4 = tid + i * 256;
            int r = f4 >> 4, kc = (f4 & 15) << 2;
            float4 kv = *reinterpret_cast<const float4*>(
                kbase + (size_t)(s0 + r) * (3 * CC) + kc);
            *reinterpret_cast<float4*>(Ks + r * KLD + kc) = kv;
            float4 vv = *reinterpret_cast<const float4*>(
                vbase + (size_t)(s0 + r) * (3 * CC) + kc);
            *reinterpret_cast<float4*>(Vs + r * VLD + kc) = vv;
        }
        __syncthreads();

        float sAcc[8][4];
        #pragma unroll
        for (int j = 0; j < 8; j++)
            #pragma unroll
            for (int q = 0; q < 4; q++) sAcc[j][q] = 0.f;
        #pragma unroll
        for (int ks = 0; ks < 8; ks++) {
            int kb = ks * 8;
            #pragma unroll
            for (int j = 0; j < 8; j++) {
                int n = j * 8 + gid;
                uint32_t bb[2];
                bb[0] = __float_as_uint(Ks[n * KLD + kb + tig]);
                bb[1] = __float_as_uint(Ks[n * KLD + kb + tig + 4]);
                mma8(sAcc[j], aQ[ks], bb);
            }
        }
        #pragma unroll
        for (int j = 0; j < 8; j++) {
            int sb = s0 + j * 8 + tig * 2;
            #pragma unroll
            for (int q = 0; q < 4; q++) {
                float v = sAcc[j][q] * 0.125f;
                int s_g = sb + (q & 1);
                int t_g = (q < 2) ? t0g : t1g;
                sAcc[j][q] = (s_g > t_g) ? -1e30f : v;
            }
        }
        float rm0 = -1e30f, rm1 = -1e30f;
        #pragma unroll
        for (int j = 0; j < 8; j++) {
            rm0 = fmaxf(rm0, fmaxf(sAcc[j][0], sAcc[j][1]));
            rm1 = fmaxf(rm1, fmaxf(sAcc[j][2], sAcc[j][3]));
        }
        #pragma unroll
        for (int o = 1; o <= 2; o <<= 1) {
            rm0 = fmaxf(rm0, __shfl_xor_sync(0xffffffffu, rm0, o));
            rm1 = fmaxf(rm1, __shfl_xor_sync(0xffffffffu, rm1, o));
        }
        float nm0 = fmaxf(m0, rm0), nm1 = fmaxf(m1, rm1);
        float a0 = __expf(m0 - nm0), a1 = __expf(m1 - nm1);
        float rs0 = 0.f, rs1 = 0.f;
        #pragma unroll
        for (int j = 0; j < 8; j++) {
            int sb = (j * 8 + tig * 2) * PLD;
            float p0 = __expf(sAcc[j][0] - nm0);
            float p1 = __expf(sAcc[j][1] - nm0);
            float p2 = __expf(sAcc[j][2] - nm1);
            float p3 = __expf(sAcc[j][3] - nm1);
            rs0 += p0 + p1; rs1 += p2 + p3;
            int tc0 = wrow + gid, tc1 = tc0 + 8;
            Ps[sb       + tc0] = tf32r(p0);
            Ps[sb + PLD + tc0] = tf32r(p1);
            Ps[sb       + tc1] = tf32r(p2);
            Ps[sb + PLD + tc1] = tf32r(p3);
        }
        #pragma unroll
        for (int o = 1; o <= 2; o <<= 1) {
            rs0 += __shfl_xor_sync(0xffffffffu, rs0, o);
            rs1 += __shfl_xor_sync(0xffffffffu, rs1, o);
        }
        l0 = l0 * a0 + rs0;
        l1 = l1 * a1 + rs1;
        m0 = nm0; m1 = nm1;
        #pragma unroll
        for (int j = 0; j < 8; j++) {
            oAcc[j][0] *= a0; oAcc[j][1] *= a0;
            oAcc[j][2] *= a1; oAcc[j][3] *= a1;
        }
        __syncwarp();
        #pragma unroll
        for (int ks = 0; ks < 8; ks++) {
            int kb = ks * 8;
            uint32_t aP[4];
            int mr = wrow + gid;
            aP[0] = __float_as_uint(Ps[(kb + tig    ) * PLD + mr    ]);
            aP[1] = __float_as_uint(Ps[(kb + tig    ) * PLD + mr + 8]);
            aP[2] = __float_as_uint(Ps[(kb + tig + 4) * PLD + mr    ]);
            aP[3] = __float_as_uint(Ps[(kb + tig + 4) * PLD + mr + 8]);
            #pragma unroll
            for (int j = 0; j < 8; j++) {
                int n = j * 8 + gid;
                uint32_t bb[2];
                bb[0] = __float_as_uint(Vs[(kb + tig    ) * VLD + n]);
                bb[1] = __float_as_uint(Vs[(kb + tig + 4) * VLD + n]);
                mma8(oAcc[j], aP, bb);
            }
        }
    }
    float inv0 = 1.f / l0, inv1 = 1.f / l1;
    __half* o0 = outp + (size_t)(b * TT + t0g) * CC + h * HDIM;
    __half* o1 = outp + (size_t)(b * TT + t1g) * CC + h * HDIM;
    #pragma unroll
    for (int j = 0; j < 8; j++) {
        int d = j * 8 + tig * 2;
        o0[d]     = __float2half_rn(oAcc[j][0] * inv0);
        o0[d + 1] = __float2half_rn(oAcc[j][1] * inv0);
        o1[d]     = __float2half_rn(oAcc[j][2] * inv1);
        o1[d + 1] = __float2half_rn(oAcc[j][3] * inv1);
    }
}

// ---------------- launch ------------------------------------------------------
extern "C" void kernel_launch(void* const* d_in, const int* in_sizes, int n_in,
                              void* d_out, int out_size) {
    const int*   x      = (const int*)  d_in[0];
    const int*   target = (const int*)  d_in[1];
    const float* tok    = (const float*)d_in[2];
    const float* pos    = (const float*)d_in[3];
    const float* ln1s   = (const float*)d_in[4];
    const float* ln1b   = (const float*)d_in[5];
    const float* wq     = (const float*)d_in[6];
    const float* wk     = (const float*)d_in[7];
    const float* wv     = (const float*)d_in[8];
    const float* wproj  = (const float*)d_in[9];
    const float* bproj  = (const float*)d_in[10];
    const float* ln2s   = (const float*)d_in[11];
    const float* ln2b   = (const float*)d_in[12];
    const float* wff1   = (const float*)d_in[13];
    const float* bff1   = (const float*)d_in[14];
    const float* wff2   = (const float*)d_in[15];
    const float* bff2   = (const float*)d_in[16];
    const float* lnfs   = (const float*)d_in[17];
    const float* lnfb   = (const float*)d_in[18];
    const float* lmw    = (const float*)d_in[19];
    const float* lmb    = (const float*)d_in[20];
    float* out = (float*)d_out;

    float  *p_h, *p_qkv, *p_lsem, *p_lses;
    __half *p_ainh, *p_attnh, *p_ffh, *p_wqkvT, *p_wpT, *p_w1T, *p_w2T, *p_lmwT;
    cudaGetSymbolAddress((void**)&p_h,     g_h);
    cudaGetSymbolAddress((void**)&p_qkv,   g_qkv);
    cudaGetSymbolAddress((void**)&p_lsem,  g_lsem);
    cudaGetSymbolAddress((void**)&p_lses,  g_lses);
    cudaGetSymbolAddress((void**)&p_ainh,  g_ainh);
    cudaGetSymbolAddress((void**)&p_attnh, g_attnh);
    cudaGetSymbolAddress((void**)&p_ffh,   g_ffh);
    cudaGetSymbolAddress((void**)&p_wqkvT, g_wqkvT);
    cudaGetSymbolAddress((void**)&p_wpT,   g_wpT);
    cudaGetSymbolAddress((void**)&p_w1T,   g_w1T);
    cudaGetSymbolAddress((void**)&p_w2T,   g_w2T);
    cudaGetSymbolAddress((void**)&p_lmwT,  g_lmwT);

    static int attr_done = 0;
    if (!attr_done) {
        cudaFuncSetAttribute(flash_kernel,
                             cudaFuncAttributeMaxDynamicSharedMemorySize, FSMEM);
        cudaFuncSetAttribute(gemm_fp16_kernel,
                             cudaFuncAttributeMaxDynamicSharedMemorySize, HSMEM);
        attr_done = 1;
    }

    prep_kernel<<<T_ALL, dim3(32, 8)>>>(wq, wk, wv, wproj, wff1, wff2, lmw);
    embed_kernel<<<(BT * CC + 255) / 256, 256>>>(x, tok, pos);

    dim3 gQKV(12, 32), gC2(4, 32), gFF(16, 32), gV(GXV, 32);
    dim3 gFA(TT / FBQ, BHZ);

    for (int l = 0; l < LLAY; l++) {
        ln_kernel<<<BT, 256>>>(p_h, ln1s + l * CC, ln1b + l * CC, p_ainh);
        gemm_fp16_kernel<<<gQKV, 256, HSMEM>>>(
            p_ainh, p_wqkvT + (size_t)l * 3 * CC * CC, p_qkv, nullptr,
            3 * CC, CC, nullptr, nullptr, 0, 1, nullptr, nullptr, 0);
        flash_kernel<<<gFA, 256, FSMEM>>>(p_qkv, p_attnh);
        gemm_fp16_kernel<<<gC2, 256, HSMEM>>>(
            p_attnh, p_wpT + (size_t)l * CC * CC, p_h, nullptr,
            CC, CC, bproj + l * CC, p_h, 0, 0, nullptr, nullptr, 0);
        ln_kernel<<<BT, 256>>>(p_h, ln2s + l * CC, ln2b + l * CC, p_ainh);
        gemm_fp16_kernel<<<gFF, 256, HSMEM>>>(
            p_ainh, p_w1T + (size_t)l * FFD * CC, nullptr, p_ffh,
            FFD, CC, bff1 + l * FFD, nullptr, 1, 0, nullptr, nullptr, 0);
        gemm_fp16_kernel<<<gC2, 256, HSMEM>>>(
            p_ffh, p_w2T + (size_t)l * CC * FFD, p_h, nullptr,
            CC, FFD, bff2 + l * CC, p_h, 0, 0, nullptr, nullptr, 0);
    }

    ln_kernel<<<BT, 256>>>(p_h, lnfs, lnfb, p_ainh);
    gemm_fp16_kernel<<<gV, 256, HSMEM>>>(
        p_ainh, p_lmwT, out, nullptr, VV, CC, lmb, nullptr, 0, 0,
        p_lsem, p_lses, GXV);

    if ((long long)out_size > (long long)BT * VV) {
        zero_loss_kernel<<<1, 1>>>();
        loss_reduce_kernel<<<BT, 128>>>(out, target, GXV);
        finalize_loss_kernel<<<1, 1>>>(out);
    }
}